// round 12
// baseline (speedup 1.0000x reference)
#include <cuda_runtime.h>
#include <cuda_bf16.h>
#include <cstdint>
#include <math.h>

// Problem constants (fixed shapes from reference)
#define D_MODEL 1024
#define N_HEADS 16
#define HEAD_D  64
#define NB      2
#define LSEQ    2048
#define MTOT    (NB * LSEQ)   // 4096 rows total

#define XSZ ((size_t)MTOT * D_MODEL)     // 4M elements
#define WSZ ((size_t)D_MODEL * D_MODEL)  // 1M elements

// ---------------------------------------------------------------------------
// Scratch (allocation-free rule: __device__ globals) — all bf16 hi/lo pairs
// ---------------------------------------------------------------------------
__device__ __nv_bfloat16 g_xh[3][XSZ];   // q/k/v inputs hi
__device__ __nv_bfloat16 g_xl[3][XSZ];   // lo
__device__ __nv_bfloat16 g_wh[4][WSZ];   // Wq/Wk/Wv/Wo hi
__device__ __nv_bfloat16 g_wl[4][WSZ];   // lo
__device__ __nv_bfloat16 g_qh[XSZ];      // projected Q hi/lo
__device__ __nv_bfloat16 g_ql[XSZ];
__device__ __nv_bfloat16 g_kh[XSZ];
__device__ __nv_bfloat16 g_kl[XSZ];
__device__ __nv_bfloat16 g_vh[XSZ];
__device__ __nv_bfloat16 g_vl[XSZ];
__device__ __nv_bfloat16 g_ah[XSZ];      // attn out hi/lo
__device__ __nv_bfloat16 g_al[XSZ];

// ---------------------------------------------------------------------------
// Small helpers
// ---------------------------------------------------------------------------
__device__ __forceinline__ uint32_t smem_u32(const void* p) {
    uint32_t a;
    asm("{ .reg .u64 t; cvta.to.shared.u64 t, %1; cvt.u32.u64 %0, t; }"
        : "=r"(a) : "l"(p));
    return a;
}
__device__ __forceinline__ void split2(float x, float y, uint32_t& hi, uint32_t& lo) {
    __nv_bfloat16 hx = __float2bfloat16_rn(x), hy = __float2bfloat16_rn(y);
    __nv_bfloat162 hp; hp.x = hx; hp.y = hy;
    hi = *reinterpret_cast<uint32_t*>(&hp);
    __nv_bfloat162 lp = __floats2bfloat162_rn(x - __bfloat162float(hx),
                                              y - __bfloat162float(hy));
    lo = *reinterpret_cast<uint32_t*>(&lp);
}
__device__ __forceinline__ void mma16816(float* c, const uint32_t* a, const uint32_t* b) {
    asm volatile(
        "mma.sync.aligned.m16n8k16.row.col.f32.bf16.bf16.f32 "
        "{%0,%1,%2,%3}, {%4,%5,%6,%7}, {%8,%9}, {%0,%1,%2,%3};"
        : "+f"(c[0]), "+f"(c[1]), "+f"(c[2]), "+f"(c[3])
        : "r"(a[0]), "r"(a[1]), "r"(a[2]), "r"(a[3]), "r"(b[0]), "r"(b[1]));
}
__device__ __forceinline__ void ldsm_x4(uint32_t* r, uint32_t a) {
    asm volatile("ldmatrix.sync.aligned.m8n8.x4.shared.b16 {%0,%1,%2,%3},[%4];"
                 : "=r"(r[0]), "=r"(r[1]), "=r"(r[2]), "=r"(r[3]) : "r"(a));
}
__device__ __forceinline__ void ldsm_x2(uint32_t* r, uint32_t a) {
    asm volatile("ldmatrix.sync.aligned.m8n8.x2.shared.b16 {%0,%1},[%2];"
                 : "=r"(r[0]), "=r"(r[1]) : "r"(a));
}
__device__ __forceinline__ void ldsm_x2t(uint32_t* r, uint32_t a) {
    asm volatile("ldmatrix.sync.aligned.m8n8.x2.trans.shared.b16 {%0,%1},[%2];"
                 : "=r"(r[0]), "=r"(r[1]) : "r"(a));
}
#define CP16(dst, src) \
    asm volatile("cp.async.cg.shared.global [%0], [%1], 16;" \
                 :: "r"(dst), "l"(src) : "memory")
#define CP_COMMIT() asm volatile("cp.async.commit_group;" ::: "memory")
#define CP_WAIT(n)  asm volatile("cp.async.wait_group %0;" :: "n"(n) : "memory")

// ---------------------------------------------------------------------------
// Fused fp32 -> bf16 hi/lo split for all 7 tensors. blockIdx.y = tensor.
// ---------------------------------------------------------------------------
__global__ __launch_bounds__(256)
void split_all_kernel(const float* __restrict__ sx0, const float* __restrict__ sx1,
                      const float* __restrict__ sx2,
                      const float* __restrict__ sw0, const float* __restrict__ sw1,
                      const float* __restrict__ sw2, const float* __restrict__ sw3,
                      __nv_bfloat16* __restrict__ xh, __nv_bfloat16* __restrict__ xl,
                      __nv_bfloat16* __restrict__ wh, __nv_bfloat16* __restrict__ wl)
{
    const int t = blockIdx.y;
    const float* src;
    __nv_bfloat16 *hi, *lo;
    int n4;
    if (t < 3) {
        src = (t == 0) ? sx0 : (t == 1) ? sx1 : sx2;
        hi = xh + (size_t)t * XSZ;
        lo = xl + (size_t)t * XSZ;
        n4 = (int)(XSZ / 4);
    } else {
        int w = t - 3;
        src = (w == 0) ? sw0 : (w == 1) ? sw1 : (w == 2) ? sw2 : sw3;
        hi = wh + (size_t)w * WSZ;
        lo = wl + (size_t)w * WSZ;
        n4 = (int)(WSZ / 4);
    }
    int i = blockIdx.x * blockDim.x + threadIdx.x;
    if (i >= n4) return;
    float4 v = ((const float4*)src)[i];
    uint32_t h0, l0, h1, l1;
    split2(v.x, v.y, h0, l0);
    split2(v.z, v.w, h1, l1);
    ((uint2*)hi)[i] = make_uint2(h0, h1);
    ((uint2*)lo)[i] = make_uint2(l0, l1);
}

// ---------------------------------------------------------------------------
// GEMM core (round-10 memory layout + pipeline — the proven-fast one).
// ONLY change vs round 10: product-major MMA order in compute_chunk
// (same-accumulator dependency chains spaced 4 apart instead of 1).
// ---------------------------------------------------------------------------
#define ASTR 40                     // smem row stride (bf16), conflict-free
#define GARR (128 * ASTR)           // elements per array (10240 B)
#define GSTAGE (4 * GARR)           // Ah,Al,Bh,Bl per stage
#define GSMEM (2 * GSTAGE * 2)      // 81920 B total (2 stages)

struct GemmCore {
    uint32_t uAh[2], uAl[2], uBh[2], uBl[2];
    uint32_t stoff, aoff, boff;
    int lrow, lhalf, warp_m, warp_n, r0, c0;
    float acc[4][4][4];

    __device__ __forceinline__ void init(__nv_bfloat16* gsm, int tid) {
        const int lane = tid & 31;
        const int wid  = tid >> 5;
        warp_m = wid >> 2;
        warp_n = wid & 3;
        lrow  = tid >> 1;
        lhalf = (tid & 1) * 16;
        r0 = lane >> 2;
        c0 = (lane & 3) * 2;
        uint32_t uBase = smem_u32(gsm);
#pragma unroll
        for (int s = 0; s < 2; s++) {
            uint32_t sb = uBase + s * GSTAGE * 2;
            uAh[s] = sb;
            uAl[s] = sb + GARR * 2;
            uBh[s] = sb + 2 * GARR * 2;
            uBl[s] = sb + 3 * GARR * 2;
        }
        stoff = (uint32_t)(lrow * ASTR + lhalf) * 2;
        const int ja = lane >> 3, ra = lane & 7;
        aoff = (uint32_t)(((warp_m * 64 + (ja & 1) * 8 + ra) * ASTR + (ja >> 1) * 8) * 2);
        boff = (uint32_t)(((warp_n * 32 + (ja >> 1) * 8 + ra) * ASTR + (ja & 1) * 8) * 2);
#pragma unroll
        for (int mf = 0; mf < 4; mf++)
#pragma unroll
            for (int nf = 0; nf < 4; nf++)
#pragma unroll
                for (int r = 0; r < 4; r++) acc[mf][nf][r] = 0.f;
    }

    __device__ __forceinline__ void load_chunk(
        const __nv_bfloat16* Xh, const __nv_bfloat16* Xl,
        const __nv_bfloat16* Wh, const __nv_bfloat16* Wl,
        int bm, int bn, int ch, int s)
    {
        const int kofs = ch * 32;
        const size_t xoff = (size_t)(bm + lrow) * D_MODEL + kofs + lhalf;
        const size_t woff = (size_t)(bn + lrow) * D_MODEL + kofs + lhalf;
        CP16(uAh[s] + stoff,      Xh + xoff);
        CP16(uAh[s] + stoff + 16, Xh + xoff + 8);
        CP16(uAl[s] + stoff,      Xl + xoff);
        CP16(uAl[s] + stoff + 16, Xl + xoff + 8);
        CP16(uBh[s] + stoff,      Wh + woff);
        CP16(uBh[s] + stoff + 16, Wh + woff + 8);
        CP16(uBl[s] + stoff,      Wl + woff);
        CP16(uBl[s] + stoff + 16, Wl + woff + 8);
        CP_COMMIT();
    }

    __device__ __forceinline__ void compute_chunk(int s) {
#pragma unroll
        for (int kk = 0; kk < 32; kk += 16) {
            // B fragments: 2 x4 loads per (h,l) cover nf 0..3
            uint32_t bh[4][2], bl[4][2], t[4];
            ldsm_x4(t, uBh[s] + boff + kk * 2);
            bh[0][0] = t[0]; bh[0][1] = t[1]; bh[1][0] = t[2]; bh[1][1] = t[3];
            ldsm_x4(t, uBh[s] + boff + (16 * ASTR + kk) * 2);
            bh[2][0] = t[0]; bh[2][1] = t[1]; bh[3][0] = t[2]; bh[3][1] = t[3];
            ldsm_x4(t, uBl[s] + boff + kk * 2);
            bl[0][0] = t[0]; bl[0][1] = t[1]; bl[1][0] = t[2]; bl[1][1] = t[3];
            ldsm_x4(t, uBl[s] + boff + (16 * ASTR + kk) * 2);
            bl[2][0] = t[0]; bl[2][1] = t[1]; bl[3][0] = t[2]; bl[3][1] = t[3];

#pragma unroll
            for (int mf = 0; mf < 4; mf++) {
                uint32_t ah[4], al[4];
                ldsm_x4(ah, uAh[s] + aoff + (mf * 16 * ASTR + kk) * 2);
                ldsm_x4(al, uAl[s] + aoff + (mf * 16 * ASTR + kk) * 2);
                // product-major: same-acc chains spaced by 4 (was 1).
                // Per-acc accumulation order unchanged (hh -> hl -> lh).
#pragma unroll
                for (int nf = 0; nf < 4; nf++) mma16816(acc[mf][nf], ah, bh[nf]);
#pragma unroll
                for (int nf = 0; nf < 4; nf++) mma16816(acc[mf][nf], ah, bl[nf]);
#pragma unroll
                for (int nf = 0; nf < 4; nf++) mma16816(acc[mf][nf], al, bh[nf]);
            }
        }
    }

    __device__ __forceinline__ void run(
        const __nv_bfloat16* Xh, const __nv_bfloat16* Xl,
        const __nv_bfloat16* Wh, const __nv_bfloat16* Wl, int bm, int bn)
    {
        load_chunk(Xh, Xl, Wh, Wl, bm, bn, 0, 0);
        const int NCH = D_MODEL / 32;   // 32
        for (int ch = 0; ch < NCH; ch++) {
            const int s = ch & 1;
            if (ch + 1 < NCH) {
                load_chunk(Xh, Xl, Wh, Wl, bm, bn, ch + 1, s ^ 1);
                CP_WAIT(1);
            } else {
                CP_WAIT(0);
            }
            __syncthreads();
            compute_chunk(s);
            __syncthreads();
        }
    }
};

// Batched QKV projection: blockIdx.z selects (input, weight, bias, output).
__global__ __launch_bounds__(256, 2)
void gemm_qkv_kernel(const __nv_bfloat16* __restrict__ xh, const __nv_bfloat16* __restrict__ xl,
                     const __nv_bfloat16* __restrict__ wh, const __nv_bfloat16* __restrict__ wl,
                     const float* __restrict__ bq, const float* __restrict__ bk,
                     const float* __restrict__ bv,
                     __nv_bfloat16* __restrict__ qh, __nv_bfloat16* __restrict__ ql,
                     __nv_bfloat16* __restrict__ kh, __nv_bfloat16* __restrict__ kl,
                     __nv_bfloat16* __restrict__ vh, __nv_bfloat16* __restrict__ vl)
{
    extern __shared__ __nv_bfloat16 gsm[];
    const int t  = blockIdx.z;
    const int bm = blockIdx.y * 128;
    const int bn = blockIdx.x * 128;

    const __nv_bfloat16* Xh = xh + (size_t)t * XSZ;
    const __nv_bfloat16* Xl = xl + (size_t)t * XSZ;
    const __nv_bfloat16* Wh = wh + (size_t)t * WSZ;
    const __nv_bfloat16* Wl = wl + (size_t)t * WSZ;
    const float* bias = (t == 0) ? bq : (t == 1) ? bk : bv;
    __nv_bfloat16* Ch = (t == 0) ? qh : (t == 1) ? kh : vh;
    __nv_bfloat16* Cl = (t == 0) ? ql : (t == 1) ? kl : vl;

    GemmCore g;
    g.init(gsm, threadIdx.x);
    g.run(Xh, Xl, Wh, Wl, bm, bn);

#pragma unroll
    for (int mf = 0; mf < 4; mf++) {
        int row = bm + g.warp_m * 64 + mf * 16 + g.r0;
#pragma unroll
        for (int nf = 0; nf < 4; nf++) {
            int col = bn + g.warp_n * 32 + nf * 8 + g.c0;
            float2 bv2 = *(const float2*)(bias + col);
            uint32_t h0, l0, h1, l1;
            split2(g.acc[mf][nf][0] + bv2.x, g.acc[mf][nf][1] + bv2.y, h0, l0);
            split2(g.acc[mf][nf][2] + bv2.x, g.acc[mf][nf][3] + bv2.y, h1, l1);
            *(uint32_t*)(Ch + (size_t)row * D_MODEL + col)       = h0;
            *(uint32_t*)(Cl + (size_t)row * D_MODEL + col)       = l0;
            *(uint32_t*)(Ch + (size_t)(row + 8) * D_MODEL + col) = h1;
            *(uint32_t*)(Cl + (size_t)(row + 8) * D_MODEL + col) = l1;
        }
    }
}

// Output projection: fp32 out.
__global__ __launch_bounds__(256, 2)
void gemm_o_kernel(const __nv_bfloat16* __restrict__ Xh, const __nv_bfloat16* __restrict__ Xl,
                   const __nv_bfloat16* __restrict__ Wh, const __nv_bfloat16* __restrict__ Wl,
                   const float* __restrict__ bias, float* __restrict__ Cf)
{
    extern __shared__ __nv_bfloat16 gsm[];
    const int bm = blockIdx.y * 128;
    const int bn = blockIdx.x * 128;

    GemmCore g;
    g.init(gsm, threadIdx.x);
    g.run(Xh, Xl, Wh, Wl, bm, bn);

#pragma unroll
    for (int mf = 0; mf < 4; mf++) {
        int row = bm + g.warp_m * 64 + mf * 16 + g.r0;
#pragma unroll
        for (int nf = 0; nf < 4; nf++) {
            int col = bn + g.warp_n * 32 + nf * 8 + g.c0;
            float2 bv2 = *(const float2*)(bias + col);
            *(float2*)(Cf + (size_t)row * D_MODEL + col) =
                make_float2(g.acc[mf][nf][0] + bv2.x, g.acc[mf][nf][1] + bv2.y);
            *(float2*)(Cf + (size_t)(row + 8) * D_MODEL + col) =
                make_float2(g.acc[mf][nf][2] + bv2.x, g.acc[mf][nf][3] + bv2.y);
        }
    }
}

// ---------------------------------------------------------------------------
// Flash attention (causal), round-7 version (measured fastest):
// 64 Q rows per CTA, 128 threads = 4 warps (16 rows each), K/V double-buffered
// via cp.async, one barrier per tile, x2/x2t B-fragment loads.
// ---------------------------------------------------------------------------
#define FA_STR 72                   // [64][72] bf16 tiles, conflict-free ldmatrix
#define FA_TILE (64 * FA_STR)       // elements per array
#define FT2 (FA_TILE * 2)           // bytes per array (9216)
#define FA_SMEM (10 * FT2)          // Q(2) + 2 stages x KV(4) = 92160 B

__global__ __launch_bounds__(128, 2)
void flash_mma_kernel(const __nv_bfloat16* __restrict__ Qh_g, const __nv_bfloat16* __restrict__ Ql_g,
                      const __nv_bfloat16* __restrict__ Kh_g, const __nv_bfloat16* __restrict__ Kl_g,
                      const __nv_bfloat16* __restrict__ Vh_g, const __nv_bfloat16* __restrict__ Vl_g,
                      __nv_bfloat16* __restrict__ Oh_g, __nv_bfloat16* __restrict__ Ol_g)
{
    extern __shared__ __nv_bfloat16 fsm[];
    __nv_bfloat16* sQh = fsm;
    __nv_bfloat16* sQl = fsm + FA_TILE;

    const int tid  = threadIdx.x;
    const int lane = tid & 31;
    const int wid  = tid >> 5;
    const int qt   = blockIdx.x;
    const int h    = blockIdx.y;
    const int n    = blockIdx.z;

    const uint32_t uQh = smem_u32(sQh);
    const uint32_t uQl = smem_u32(sQl);
    const uint32_t uKV0 = uQh + 2 * FT2;   // stage 0 base

    const float scale = 0.125f;   // 1/sqrt(64)
    const int wr = wid * 16;      // warp's Q-row base within tile
    const int r0 = lane >> 2;     // 0..7
    const int c0 = (lane & 3) * 2;

    // Load Q tile (hi/lo), natural [row][d] layout (plain vector loads).
    const size_t qrow0 = (size_t)(n * LSEQ + qt * 64);
    const size_t gq = qrow0 * D_MODEL + (size_t)h * HEAD_D;
#pragma unroll
    for (int i = 0; i < 4; i++) {
        int f = tid + i * 128;          // 0..511
        int row = f >> 3, c8 = (f & 7) * 8;
        int so = row * FA_STR + c8;
        size_t go = gq + (size_t)row * D_MODEL + c8;
        *(uint4*)(sQh + so) = *(const uint4*)(Qh_g + go);
        *(uint4*)(sQl + so) = *(const uint4*)(Ql_g + go);
    }

    // K/V chunk loader via cp.async (16x16B per thread)
    auto load_kv = [&](int kt, int s) {
        const uint32_t base = uKV0 + (uint32_t)s * 4 * FT2;
        const size_t gk = ((size_t)(n * LSEQ + kt * 64)) * D_MODEL + (size_t)h * HEAD_D;
#pragma unroll
        for (int i = 0; i < 4; i++) {
            int f = tid + i * 128;
            int row = f >> 3, c8 = (f & 7) * 8;
            uint32_t so = (uint32_t)(row * FA_STR + c8) * 2;
            size_t go = gk + (size_t)row * D_MODEL + c8;
            CP16(base + so,           Kh_g + go);
            CP16(base + FT2 + so,     Kl_g + go);
            CP16(base + 2 * FT2 + so, Vh_g + go);
            CP16(base + 3 * FT2 + so, Vl_g + go);
        }
        CP_COMMIT();
    };

    float oacc[8][4];
#pragma unroll
    for (int nf = 0; nf < 8; nf++)
#pragma unroll
        for (int j = 0; j < 4; j++) oacc[nf][j] = 0.f;
    float m0 = -INFINITY, m1 = -INFINITY, l0 = 0.f, l1 = 0.f;

    load_kv(0, 0);

    for (int kt = 0; kt <= qt; kt++) {
        const int s = kt & 1;
        const uint32_t uKh = uKV0 + (uint32_t)s * 4 * FT2;
        const uint32_t uKl = uKh + FT2;
        const uint32_t uVh = uKh + 2 * FT2;
        const uint32_t uVl = uKh + 3 * FT2;

        CP_WAIT(0);        // current stage's copies arrived
        __syncthreads();   // all warps done with stage s^1 + copies visible
        if (kt < qt) load_kv(kt + 1, s ^ 1);   // prefetch overlaps compute below

        // ---- S = Q K^T (hi/lo 3-product) ----
        float sacc[8][4];
#pragma unroll
        for (int nf = 0; nf < 8; nf++)
#pragma unroll
            for (int j = 0; j < 4; j++) sacc[nf][j] = 0.f;

#pragma unroll
        for (int kc = 0; kc < 4; kc++) {
            const uint32_t aoff = (uint32_t)(((wr + (lane & 15)) * FA_STR
                                  + kc * 16 + (lane >> 4) * 8) * 2);
            uint32_t aqh[4], aql[4];
            ldsm_x4(aqh, uQh + aoff);
            ldsm_x4(aql, uQl + aoff);
            const uint32_t brow = (lane & 7);
            const uint32_t bk8  = ((lane >> 3) & 1) * 8;
#pragma unroll
            for (int nf = 0; nf < 8; nf++) {
                const uint32_t boff = (uint32_t)(((nf * 8 + brow) * FA_STR
                                      + kc * 16 + bk8) * 2);
                uint32_t bkh[2], bkl[2];
                ldsm_x2(bkh, uKh + boff);
                ldsm_x2(bkl, uKl + boff);
                mma16816(sacc[nf], aqh, bkh);
                mma16816(sacc[nf], aqh, bkl);
                mma16816(sacc[nf], aql, bkh);
            }
        }

        // ---- scale + causal mask ----
        if (kt == qt) {
#pragma unroll
            for (int nf = 0; nf < 8; nf++) {
                int col = nf * 8 + c0;
                int lrA = wr + r0, lrB = wr + r0 + 8;
                sacc[nf][0] = (col     > lrA) ? -INFINITY : sacc[nf][0] * scale;
                sacc[nf][1] = (col + 1 > lrA) ? -INFINITY : sacc[nf][1] * scale;
                sacc[nf][2] = (col     > lrB) ? -INFINITY : sacc[nf][2] * scale;
                sacc[nf][3] = (col + 1 > lrB) ? -INFINITY : sacc[nf][3] * scale;
            }
        } else {
#pragma unroll
            for (int nf = 0; nf < 8; nf++)
#pragma unroll
                for (int j = 0; j < 4; j++) sacc[nf][j] *= scale;
        }

        // ---- online softmax ----
        float mx0 = -INFINITY, mx1 = -INFINITY;
#pragma unroll
        for (int nf = 0; nf < 8; nf++) {
            mx0 = fmaxf(mx0, fmaxf(sacc[nf][0], sacc[nf][1]));
            mx1 = fmaxf(mx1, fmaxf(sacc[nf][2], sacc[nf][3]));
        }
        mx0 = fmaxf(mx0, __shfl_xor_sync(0xffffffffu, mx0, 1));
        mx0 = fmaxf(mx0, __shfl_xor_sync(0xffffffffu, mx0, 2));
        mx1 = fmaxf(mx1, __shfl_xor_sync(0xffffffffu, mx1, 1));
        mx1 = fmaxf(mx1, __shfl_xor_sync(0xffffffffu, mx1, 2));
        float mn0 = fmaxf(m0, mx0), mn1 = fmaxf(m1, mx1);
        float corr0 = __expf(m0 - mn0), corr1 = __expf(m1 - mn1);
        m0 = mn0; m1 = mn1;
        float rs0 = 0.f, rs1 = 0.f;
#pragma unroll
        for (int nf = 0; nf < 8; nf++) {
            sacc[nf][0] = __expf(sacc[nf][0] - m0);
            sacc[nf][1] = __expf(sacc[nf][1] - m0);
            sacc[nf][2] = __expf(sacc[nf][2] - m1);
            sacc[nf][3] = __expf(sacc[nf][3] - m1);
            rs0 += sacc[nf][0] + sacc[nf][1];
            rs1 += sacc[nf][2] + sacc[nf][3];
        }
        rs0 += __shfl_xor_sync(0xffffffffu, rs0, 1);
        rs0 += __shfl_xor_sync(0xffffffffu, rs0, 2);
        rs1 += __shfl_xor_sync(0xffffffffu, rs1, 1);
        rs1 += __shfl_xor_sync(0xffffffffu, rs1, 2);
        l0 = l0 * corr0 + rs0;
        l1 = l1 * corr1 + rs1;
#pragma unroll
        for (int nf = 0; nf < 8; nf++) {
            oacc[nf][0] *= corr0; oacc[nf][1] *= corr0;
            oacc[nf][2] *= corr1; oacc[nf][3] *= corr1;
        }

        // ---- O += P V (hi/lo 3-product, P repacked from accumulators) ----
#pragma unroll
        for (int kc = 0; kc < 4; kc++) {
            uint32_t aph[4], apl[4];
            split2(sacc[2 * kc][0],     sacc[2 * kc][1],     aph[0], apl[0]);
            split2(sacc[2 * kc][2],     sacc[2 * kc][3],     aph[1], apl[1]);
            split2(sacc[2 * kc + 1][0], sacc[2 * kc + 1][1], aph[2], apl[2]);
            split2(sacc[2 * kc + 1][2], sacc[2 * kc + 1][3], aph[3], apl[3]);
            const uint32_t vrow = (uint32_t)(kc * 16 + (lane & 15));
#pragma unroll
            for (int nf = 0; nf < 8; nf++) {
                const uint32_t voff = (uint32_t)((vrow * FA_STR + nf * 8) * 2);
                uint32_t bvh[2], bvl[2];
                ldsm_x2t(bvh, uVh + voff);
                ldsm_x2t(bvl, uVl + voff);
                mma16816(oacc[nf], aph, bvh);
                mma16816(oacc[nf], aph, bvl);
                mma16816(oacc[nf], apl, bvh);
            }
        }
    }

    // ---- epilogue: normalize, split to bf16 hi/lo, store ----
    float inv0 = 1.f / l0, inv1 = 1.f / l1;
    const size_t goA = (qrow0 + wr + r0) * D_MODEL + (size_t)h * HEAD_D;
    const size_t goB = goA + 8 * D_MODEL;
#pragma unroll
    for (int nf = 0; nf < 8; nf++) {
        int d = nf * 8 + c0;
        uint32_t h0, lo0, h1, lo1;
        split2(oacc[nf][0] * inv0, oacc[nf][1] * inv0, h0, lo0);
        split2(oacc[nf][2] * inv1, oacc[nf][3] * inv1, h1, lo1);
        *(uint32_t*)(Oh_g + goA + d) = h0;
        *(uint32_t*)(Ol_g + goA + d) = lo0;
        *(uint32_t*)(Oh_g + goB + d) = h1;
        *(uint32_t*)(Ol_g + goB + d) = lo1;
    }
}

// ---------------------------------------------------------------------------
// kernel_launch: split(1) -> gemm_qkv(1) -> flash(1) -> gemm_o(1)
// ---------------------------------------------------------------------------
extern "C" void kernel_launch(void* const* d_in, const int* in_sizes, int n_in,
                              void* d_out, int out_size)
{
    const float* queries = (const float*)d_in[0];
    const float* keys    = (const float*)d_in[1];
    const float* values  = (const float*)d_in[2];
    const float* Wq = (const float*)d_in[3];
    const float* bq = (const float*)d_in[4];
    const float* Wk = (const float*)d_in[5];
    const float* bk = (const float*)d_in[6];
    const float* Wv = (const float*)d_in[7];
    const float* bv = (const float*)d_in[8];
    const float* Wo = (const float*)d_in[9];
    const float* bo = (const float*)d_in[10];
    float* out = (float*)d_out;

    __nv_bfloat16 *xh, *xl, *wh, *wl, *qh, *ql, *kh, *kl, *vh, *vl, *ah, *al;
    cudaGetSymbolAddress((void**)&xh, g_xh);
    cudaGetSymbolAddress((void**)&xl, g_xl);
    cudaGetSymbolAddress((void**)&wh, g_wh);
    cudaGetSymbolAddress((void**)&wl, g_wl);
    cudaGetSymbolAddress((void**)&qh, g_qh);
    cudaGetSymbolAddress((void**)&ql, g_ql);
    cudaGetSymbolAddress((void**)&kh, g_kh);
    cudaGetSymbolAddress((void**)&kl, g_kl);
    cudaGetSymbolAddress((void**)&vh, g_vh);
    cudaGetSymbolAddress((void**)&vl, g_vl);
    cudaGetSymbolAddress((void**)&ah, g_ah);
    cudaGetSymbolAddress((void**)&al, g_al);

    cudaFuncSetAttribute(flash_mma_kernel,
                         cudaFuncAttributeMaxDynamicSharedMemorySize, FA_SMEM);
    cudaFuncSetAttribute(gemm_qkv_kernel,
                         cudaFuncAttributeMaxDynamicSharedMemorySize, GSMEM);
    cudaFuncSetAttribute(gemm_o_kernel,
                         cudaFuncAttributeMaxDynamicSharedMemorySize, GSMEM);

    // 1) Fused split of all 7 tensors
    dim3 sGrd((unsigned)(XSZ / 4 / 256), 7);
    split_all_kernel<<<sGrd, 256>>>(queries, keys, values, Wq, Wk, Wv, Wo,
                                    xh, xl, wh, wl);

    // 2) Batched Q/K/V projections (z = tensor)
    dim3 gGrd(D_MODEL / 128, MTOT / 128, 3);   // (8, 32, 3)
    gemm_qkv_kernel<<<gGrd, 256, GSMEM>>>(xh, xl, wh, wl, bq, bk, bv,
                                          qh, ql, kh, kl, vh, vl);

    // 3) Attention (64-row Q tiles)
    dim3 aGrd(LSEQ / 64, N_HEADS, NB);         // (32, 16, 2)
    flash_mma_kernel<<<aGrd, 128, FA_SMEM>>>(qh, ql, kh, kl, vh, vl, ah, al);

    // 4) Output projection: fp32 out
    dim3 oGrd(D_MODEL / 128, MTOT / 128);      // (8, 32)
    gemm_o_kernel<<<oGrd, 256, GSMEM>>>(ah, al, wh + 3 * WSZ, wl + 3 * WSZ, bo, out);
}

// round 13
// speedup vs baseline: 1.7615x; 1.7615x over previous
#include <cuda_runtime.h>
#include <cuda_bf16.h>
#include <cstdint>
#include <math.h>

// Problem constants (fixed shapes from reference)
#define D_MODEL 1024
#define N_HEADS 16
#define HEAD_D  64
#define NB      2
#define LSEQ    2048
#define MTOT    (NB * LSEQ)   // 4096 rows total

#define XSZ ((size_t)MTOT * D_MODEL)     // 4M elements
#define WSZ ((size_t)D_MODEL * D_MODEL)  // 1M elements

// ---------------------------------------------------------------------------
// Scratch (allocation-free rule: __device__ globals) — all bf16 hi/lo pairs
// ---------------------------------------------------------------------------
__device__ __nv_bfloat16 g_xh[3][XSZ];   // q/k/v inputs hi
__device__ __nv_bfloat16 g_xl[3][XSZ];   // lo
__device__ __nv_bfloat16 g_wh[4][WSZ];   // Wq/Wk/Wv/Wo hi
__device__ __nv_bfloat16 g_wl[4][WSZ];   // lo
__device__ __nv_bfloat16 g_qh[XSZ];      // projected Q hi/lo
__device__ __nv_bfloat16 g_ql[XSZ];
__device__ __nv_bfloat16 g_kh[XSZ];
__device__ __nv_bfloat16 g_kl[XSZ];
__device__ __nv_bfloat16 g_vh[XSZ];
__device__ __nv_bfloat16 g_vl[XSZ];
__device__ __nv_bfloat16 g_ah[XSZ];      // attn out hi/lo
__device__ __nv_bfloat16 g_al[XSZ];

// ---------------------------------------------------------------------------
// Small helpers
// ---------------------------------------------------------------------------
__device__ __forceinline__ uint32_t smem_u32(const void* p) {
    uint32_t a;
    asm("{ .reg .u64 t; cvta.to.shared.u64 t, %1; cvt.u32.u64 %0, t; }"
        : "=r"(a) : "l"(p));
    return a;
}
__device__ __forceinline__ void split2(float x, float y, uint32_t& hi, uint32_t& lo) {
    __nv_bfloat16 hx = __float2bfloat16_rn(x), hy = __float2bfloat16_rn(y);
    __nv_bfloat162 hp; hp.x = hx; hp.y = hy;
    hi = *reinterpret_cast<uint32_t*>(&hp);
    __nv_bfloat162 lp = __floats2bfloat162_rn(x - __bfloat162float(hx),
                                              y - __bfloat162float(hy));
    lo = *reinterpret_cast<uint32_t*>(&lp);
}
__device__ __forceinline__ void mma16816(float* c, const uint32_t* a, const uint32_t* b) {
    asm volatile(
        "mma.sync.aligned.m16n8k16.row.col.f32.bf16.bf16.f32 "
        "{%0,%1,%2,%3}, {%4,%5,%6,%7}, {%8,%9}, {%0,%1,%2,%3};"
        : "+f"(c[0]), "+f"(c[1]), "+f"(c[2]), "+f"(c[3])
        : "r"(a[0]), "r"(a[1]), "r"(a[2]), "r"(a[3]), "r"(b[0]), "r"(b[1]));
}
__device__ __forceinline__ void ldsm_x4(uint32_t* r, uint32_t a) {
    asm volatile("ldmatrix.sync.aligned.m8n8.x4.shared.b16 {%0,%1,%2,%3},[%4];"
                 : "=r"(r[0]), "=r"(r[1]), "=r"(r[2]), "=r"(r[3]) : "r"(a));
}
__device__ __forceinline__ void ldsm_x2(uint32_t* r, uint32_t a) {
    asm volatile("ldmatrix.sync.aligned.m8n8.x2.shared.b16 {%0,%1},[%2];"
                 : "=r"(r[0]), "=r"(r[1]) : "r"(a));
}
__device__ __forceinline__ void ldsm_x2t(uint32_t* r, uint32_t a) {
    asm volatile("ldmatrix.sync.aligned.m8n8.x2.trans.shared.b16 {%0,%1},[%2];"
                 : "=r"(r[0]), "=r"(r[1]) : "r"(a));
}
#define CP16(dst, src) \
    asm volatile("cp.async.cg.shared.global [%0], [%1], 16;" \
                 :: "r"(dst), "l"(src) : "memory")
#define CP_COMMIT() asm volatile("cp.async.commit_group;" ::: "memory")
#define CP_WAIT(n)  asm volatile("cp.async.wait_group %0;" :: "n"(n) : "memory")

// ---------------------------------------------------------------------------
// Fused fp32 -> bf16 hi/lo split for all 7 tensors. blockIdx.y = tensor.
// ---------------------------------------------------------------------------
__global__ __launch_bounds__(256)
void split_all_kernel(const float* __restrict__ sx0, const float* __restrict__ sx1,
                      const float* __restrict__ sx2,
                      const float* __restrict__ sw0, const float* __restrict__ sw1,
                      const float* __restrict__ sw2, const float* __restrict__ sw3,
                      __nv_bfloat16* __restrict__ xh, __nv_bfloat16* __restrict__ xl,
                      __nv_bfloat16* __restrict__ wh, __nv_bfloat16* __restrict__ wl)
{
    const int t = blockIdx.y;
    const float* src;
    __nv_bfloat16 *hi, *lo;
    int n4;
    if (t < 3) {
        src = (t == 0) ? sx0 : (t == 1) ? sx1 : sx2;
        hi = xh + (size_t)t * XSZ;
        lo = xl + (size_t)t * XSZ;
        n4 = (int)(XSZ / 4);
    } else {
        int w = t - 3;
        src = (w == 0) ? sw0 : (w == 1) ? sw1 : (w == 2) ? sw2 : sw3;
        hi = wh + (size_t)w * WSZ;
        lo = wl + (size_t)w * WSZ;
        n4 = (int)(WSZ / 4);
    }
    int i = blockIdx.x * blockDim.x + threadIdx.x;
    if (i >= n4) return;
    float4 v = ((const float4*)src)[i];
    uint32_t h0, l0, h1, l1;
    split2(v.x, v.y, h0, l0);
    split2(v.z, v.w, h1, l1);
    ((uint2*)hi)[i] = make_uint2(h0, h1);
    ((uint2*)lo)[i] = make_uint2(l0, l1);
}

// ---------------------------------------------------------------------------
// GEMM core — VERBATIM round-7/round-10 schedule (the proven-fast one).
// DO NOT modify compute_chunk or run(): four structurally different edits
// (R8/R9/R11/R12) each regressed 93us -> 214us with a spill-like signature.
// ---------------------------------------------------------------------------
#define ASTR 40                     // smem row stride (bf16), conflict-free
#define GARR (128 * ASTR)           // elements per array (10240 B)
#define GSTAGE (4 * GARR)           // Ah,Al,Bh,Bl per stage
#define GSMEM (2 * GSTAGE * 2)      // 81920 B total (2 stages)

struct GemmCore {
    uint32_t uAh[2], uAl[2], uBh[2], uBl[2];
    uint32_t stoff, aoff, boff;
    int lrow, lhalf, warp_m, warp_n, r0, c0;
    float acc[4][4][4];

    __device__ __forceinline__ void init(__nv_bfloat16* gsm, int tid) {
        const int lane = tid & 31;
        const int wid  = tid >> 5;
        warp_m = wid >> 2;
        warp_n = wid & 3;
        lrow  = tid >> 1;
        lhalf = (tid & 1) * 16;
        r0 = lane >> 2;
        c0 = (lane & 3) * 2;
        uint32_t uBase = smem_u32(gsm);
#pragma unroll
        for (int s = 0; s < 2; s++) {
            uint32_t sb = uBase + s * GSTAGE * 2;
            uAh[s] = sb;
            uAl[s] = sb + GARR * 2;
            uBh[s] = sb + 2 * GARR * 2;
            uBl[s] = sb + 3 * GARR * 2;
        }
        stoff = (uint32_t)(lrow * ASTR + lhalf) * 2;
        const int ja = lane >> 3, ra = lane & 7;
        aoff = (uint32_t)(((warp_m * 64 + (ja & 1) * 8 + ra) * ASTR + (ja >> 1) * 8) * 2);
        boff = (uint32_t)(((warp_n * 32 + (ja >> 1) * 8 + ra) * ASTR + (ja & 1) * 8) * 2);
#pragma unroll
        for (int mf = 0; mf < 4; mf++)
#pragma unroll
            for (int nf = 0; nf < 4; nf++)
#pragma unroll
                for (int r = 0; r < 4; r++) acc[mf][nf][r] = 0.f;
    }

    __device__ __forceinline__ void load_chunk(
        const __nv_bfloat16* Xh, const __nv_bfloat16* Xl,
        const __nv_bfloat16* Wh, const __nv_bfloat16* Wl,
        int bm, int bn, int ch, int s)
    {
        const int kofs = ch * 32;
        const size_t xoff = (size_t)(bm + lrow) * D_MODEL + kofs + lhalf;
        const size_t woff = (size_t)(bn + lrow) * D_MODEL + kofs + lhalf;
        CP16(uAh[s] + stoff,      Xh + xoff);
        CP16(uAh[s] + stoff + 16, Xh + xoff + 8);
        CP16(uAl[s] + stoff,      Xl + xoff);
        CP16(uAl[s] + stoff + 16, Xl + xoff + 8);
        CP16(uBh[s] + stoff,      Wh + woff);
        CP16(uBh[s] + stoff + 16, Wh + woff + 8);
        CP16(uBl[s] + stoff,      Wl + woff);
        CP16(uBl[s] + stoff + 16, Wl + woff + 8);
        CP_COMMIT();
    }

    __device__ __forceinline__ void compute_chunk(int s) {
#pragma unroll
        for (int kk = 0; kk < 32; kk += 16) {
            // B fragments: 2 x4 loads per (h,l) cover nf 0..3
            uint32_t bh[4][2], bl[4][2], t[4];
            ldsm_x4(t, uBh[s] + boff + kk * 2);
            bh[0][0] = t[0]; bh[0][1] = t[1]; bh[1][0] = t[2]; bh[1][1] = t[3];
            ldsm_x4(t, uBh[s] + boff + (16 * ASTR + kk) * 2);
            bh[2][0] = t[0]; bh[2][1] = t[1]; bh[3][0] = t[2]; bh[3][1] = t[3];
            ldsm_x4(t, uBl[s] + boff + kk * 2);
            bl[0][0] = t[0]; bl[0][1] = t[1]; bl[1][0] = t[2]; bl[1][1] = t[3];
            ldsm_x4(t, uBl[s] + boff + (16 * ASTR + kk) * 2);
            bl[2][0] = t[0]; bl[2][1] = t[1]; bl[3][0] = t[2]; bl[3][1] = t[3];

#pragma unroll
            for (int mf = 0; mf < 4; mf++) {
                uint32_t ah[4], al[4];
                ldsm_x4(ah, uAh[s] + aoff + (mf * 16 * ASTR + kk) * 2);
                ldsm_x4(al, uAl[s] + aoff + (mf * 16 * ASTR + kk) * 2);
#pragma unroll
                for (int nf = 0; nf < 4; nf++) {
                    mma16816(acc[mf][nf], ah, bh[nf]);
                    mma16816(acc[mf][nf], ah, bl[nf]);
                    mma16816(acc[mf][nf], al, bh[nf]);
                }
            }
        }
    }

    __device__ __forceinline__ void run(
        const __nv_bfloat16* Xh, const __nv_bfloat16* Xl,
        const __nv_bfloat16* Wh, const __nv_bfloat16* Wl, int bm, int bn)
    {
        load_chunk(Xh, Xl, Wh, Wl, bm, bn, 0, 0);
        const int NCH = D_MODEL / 32;   // 32
        for (int ch = 0; ch < NCH; ch++) {
            const int s = ch & 1;
            if (ch + 1 < NCH) {
                load_chunk(Xh, Xl, Wh, Wl, bm, bn, ch + 1, s ^ 1);
                CP_WAIT(1);
            } else {
                CP_WAIT(0);
            }
            __syncthreads();
            compute_chunk(s);
            __syncthreads();
        }
    }
};

// Batched QKV projection: blockIdx.z selects (input, weight, bias, output).
__global__ __launch_bounds__(256, 2)
void gemm_qkv_kernel(const __nv_bfloat16* __restrict__ xh, const __nv_bfloat16* __restrict__ xl,
                     const __nv_bfloat16* __restrict__ wh, const __nv_bfloat16* __restrict__ wl,
                     const float* __restrict__ bq, const float* __restrict__ bk,
                     const float* __restrict__ bv,
                     __nv_bfloat16* __restrict__ qh, __nv_bfloat16* __restrict__ ql,
                     __nv_bfloat16* __restrict__ kh, __nv_bfloat16* __restrict__ kl,
                     __nv_bfloat16* __restrict__ vh, __nv_bfloat16* __restrict__ vl)
{
    extern __shared__ __nv_bfloat16 gsm[];
    const int t  = blockIdx.z;
    const int bm = blockIdx.y * 128;
    const int bn = blockIdx.x * 128;

    const __nv_bfloat16* Xh = xh + (size_t)t * XSZ;
    const __nv_bfloat16* Xl = xl + (size_t)t * XSZ;
    const __nv_bfloat16* Wh = wh + (size_t)t * WSZ;
    const __nv_bfloat16* Wl = wl + (size_t)t * WSZ;
    const float* bias = (t == 0) ? bq : (t == 1) ? bk : bv;
    __nv_bfloat16* Ch = (t == 0) ? qh : (t == 1) ? kh : vh;
    __nv_bfloat16* Cl = (t == 0) ? ql : (t == 1) ? kl : vl;

    GemmCore g;
    g.init(gsm, threadIdx.x);
    g.run(Xh, Xl, Wh, Wl, bm, bn);

#pragma unroll
    for (int mf = 0; mf < 4; mf++) {
        int row = bm + g.warp_m * 64 + mf * 16 + g.r0;
#pragma unroll
        for (int nf = 0; nf < 4; nf++) {
            int col = bn + g.warp_n * 32 + nf * 8 + g.c0;
            float2 bv2 = *(const float2*)(bias + col);
            uint32_t h0, l0, h1, l1;
            split2(g.acc[mf][nf][0] + bv2.x, g.acc[mf][nf][1] + bv2.y, h0, l0);
            split2(g.acc[mf][nf][2] + bv2.x, g.acc[mf][nf][3] + bv2.y, h1, l1);
            *(uint32_t*)(Ch + (size_t)row * D_MODEL + col)       = h0;
            *(uint32_t*)(Cl + (size_t)row * D_MODEL + col)       = l0;
            *(uint32_t*)(Ch + (size_t)(row + 8) * D_MODEL + col) = h1;
            *(uint32_t*)(Cl + (size_t)(row + 8) * D_MODEL + col) = l1;
        }
    }
}

// Output projection: fp32 out.
__global__ __launch_bounds__(256, 2)
void gemm_o_kernel(const __nv_bfloat16* __restrict__ Xh, const __nv_bfloat16* __restrict__ Xl,
                   const __nv_bfloat16* __restrict__ Wh, const __nv_bfloat16* __restrict__ Wl,
                   const float* __restrict__ bias, float* __restrict__ Cf)
{
    extern __shared__ __nv_bfloat16 gsm[];
    const int bm = blockIdx.y * 128;
    const int bn = blockIdx.x * 128;

    GemmCore g;
    g.init(gsm, threadIdx.x);
    g.run(Xh, Xl, Wh, Wl, bm, bn);

#pragma unroll
    for (int mf = 0; mf < 4; mf++) {
        int row = bm + g.warp_m * 64 + mf * 16 + g.r0;
#pragma unroll
        for (int nf = 0; nf < 4; nf++) {
            int col = bn + g.warp_n * 32 + nf * 8 + g.c0;
            float2 bv2 = *(const float2*)(bias + col);
            *(float2*)(Cf + (size_t)row * D_MODEL + col) =
                make_float2(g.acc[mf][nf][0] + bv2.x, g.acc[mf][nf][1] + bv2.y);
            *(float2*)(Cf + (size_t)(row + 8) * D_MODEL + col) =
                make_float2(g.acc[mf][nf][2] + bv2.x, g.acc[mf][nf][3] + bv2.y);
        }
    }
}

// ---------------------------------------------------------------------------
// Flash attention (causal), round-7 version (measured fastest).
// ONLY change: qt runs in DESCENDING order so the heaviest CTAs (qt large,
// ~qt+1 K-tiles each) are scheduled in the first wave, shrinking the tail.
// ---------------------------------------------------------------------------
#define FA_STR 72                   // [64][72] bf16 tiles, conflict-free ldmatrix
#define FA_TILE (64 * FA_STR)       // elements per array
#define FT2 (FA_TILE * 2)           // bytes per array (9216)
#define FA_SMEM (10 * FT2)          // Q(2) + 2 stages x KV(4) = 92160 B

__global__ __launch_bounds__(128, 2)
void flash_mma_kernel(const __nv_bfloat16* __restrict__ Qh_g, const __nv_bfloat16* __restrict__ Ql_g,
                      const __nv_bfloat16* __restrict__ Kh_g, const __nv_bfloat16* __restrict__ Kl_g,
                      const __nv_bfloat16* __restrict__ Vh_g, const __nv_bfloat16* __restrict__ Vl_g,
                      __nv_bfloat16* __restrict__ Oh_g, __nv_bfloat16* __restrict__ Ol_g)
{
    extern __shared__ __nv_bfloat16 fsm[];
    __nv_bfloat16* sQh = fsm;
    __nv_bfloat16* sQl = fsm + FA_TILE;

    const int tid  = threadIdx.x;
    const int lane = tid & 31;
    const int wid  = tid >> 5;
    const int qt   = (int)(gridDim.x - 1 - blockIdx.x);   // descending work order
    const int h    = blockIdx.y;
    const int n    = blockIdx.z;

    const uint32_t uQh = smem_u32(sQh);
    const uint32_t uQl = smem_u32(sQl);
    const uint32_t uKV0 = uQh + 2 * FT2;   // stage 0 base

    const float scale = 0.125f;   // 1/sqrt(64)
    const int wr = wid * 16;      // warp's Q-row base within tile
    const int r0 = lane >> 2;     // 0..7
    const int c0 = (lane & 3) * 2;

    // Load Q tile (hi/lo), natural [row][d] layout (plain vector loads).
    const size_t qrow0 = (size_t)(n * LSEQ + qt * 64);
    const size_t gq = qrow0 * D_MODEL + (size_t)h * HEAD_D;
#pragma unroll
    for (int i = 0; i < 4; i++) {
        int f = tid + i * 128;          // 0..511
        int row = f >> 3, c8 = (f & 7) * 8;
        int so = row * FA_STR + c8;
        size_t go = gq + (size_t)row * D_MODEL + c8;
        *(uint4*)(sQh + so) = *(const uint4*)(Qh_g + go);
        *(uint4*)(sQl + so) = *(const uint4*)(Ql_g + go);
    }

    // K/V chunk loader via cp.async (16x16B per thread)
    auto load_kv = [&](int kt, int s) {
        const uint32_t base = uKV0 + (uint32_t)s * 4 * FT2;
        const size_t gk = ((size_t)(n * LSEQ + kt * 64)) * D_MODEL + (size_t)h * HEAD_D;
#pragma unroll
        for (int i = 0; i < 4; i++) {
            int f = tid + i * 128;
            int row = f >> 3, c8 = (f & 7) * 8;
            uint32_t so = (uint32_t)(row * FA_STR + c8) * 2;
            size_t go = gk + (size_t)row * D_MODEL + c8;
            CP16(base + so,           Kh_g + go);
            CP16(base + FT2 + so,     Kl_g + go);
            CP16(base + 2 * FT2 + so, Vh_g + go);
            CP16(base + 3 * FT2 + so, Vl_g + go);
        }
        CP_COMMIT();
    };

    float oacc[8][4];
#pragma unroll
    for (int nf = 0; nf < 8; nf++)
#pragma unroll
        for (int j = 0; j < 4; j++) oacc[nf][j] = 0.f;
    float m0 = -INFINITY, m1 = -INFINITY, l0 = 0.f, l1 = 0.f;

    load_kv(0, 0);

    for (int kt = 0; kt <= qt; kt++) {
        const int s = kt & 1;
        const uint32_t uKh = uKV0 + (uint32_t)s * 4 * FT2;
        const uint32_t uKl = uKh + FT2;
        const uint32_t uVh = uKh + 2 * FT2;
        const uint32_t uVl = uKh + 3 * FT2;

        CP_WAIT(0);        // current stage's copies arrived
        __syncthreads();   // all warps done with stage s^1 + copies visible
        if (kt < qt) load_kv(kt + 1, s ^ 1);   // prefetch overlaps compute below

        // ---- S = Q K^T (hi/lo 3-product) ----
        float sacc[8][4];
#pragma unroll
        for (int nf = 0; nf < 8; nf++)
#pragma unroll
            for (int j = 0; j < 4; j++) sacc[nf][j] = 0.f;

#pragma unroll
        for (int kc = 0; kc < 4; kc++) {
            const uint32_t aoff = (uint32_t)(((wr + (lane & 15)) * FA_STR
                                  + kc * 16 + (lane >> 4) * 8) * 2);
            uint32_t aqh[4], aql[4];
            ldsm_x4(aqh, uQh + aoff);
            ldsm_x4(aql, uQl + aoff);
            const uint32_t brow = (lane & 7);
            const uint32_t bk8  = ((lane >> 3) & 1) * 8;
#pragma unroll
            for (int nf = 0; nf < 8; nf++) {
                const uint32_t boff = (uint32_t)(((nf * 8 + brow) * FA_STR
                                      + kc * 16 + bk8) * 2);
                uint32_t bkh[2], bkl[2];
                ldsm_x2(bkh, uKh + boff);
                ldsm_x2(bkl, uKl + boff);
                mma16816(sacc[nf], aqh, bkh);
                mma16816(sacc[nf], aqh, bkl);
                mma16816(sacc[nf], aql, bkh);
            }
        }

        // ---- scale + causal mask ----
        if (kt == qt) {
#pragma unroll
            for (int nf = 0; nf < 8; nf++) {
                int col = nf * 8 + c0;
                int lrA = wr + r0, lrB = wr + r0 + 8;
                sacc[nf][0] = (col     > lrA) ? -INFINITY : sacc[nf][0] * scale;
                sacc[nf][1] = (col + 1 > lrA) ? -INFINITY : sacc[nf][1] * scale;
                sacc[nf][2] = (col     > lrB) ? -INFINITY : sacc[nf][2] * scale;
                sacc[nf][3] = (col + 1 > lrB) ? -INFINITY : sacc[nf][3] * scale;
            }
        } else {
#pragma unroll
            for (int nf = 0; nf < 8; nf++)
#pragma unroll
                for (int j = 0; j < 4; j++) sacc[nf][j] *= scale;
        }

        // ---- online softmax ----
        float mx0 = -INFINITY, mx1 = -INFINITY;
#pragma unroll
        for (int nf = 0; nf < 8; nf++) {
            mx0 = fmaxf(mx0, fmaxf(sacc[nf][0], sacc[nf][1]));
            mx1 = fmaxf(mx1, fmaxf(sacc[nf][2], sacc[nf][3]));
        }
        mx0 = fmaxf(mx0, __shfl_xor_sync(0xffffffffu, mx0, 1));
        mx0 = fmaxf(mx0, __shfl_xor_sync(0xffffffffu, mx0, 2));
        mx1 = fmaxf(mx1, __shfl_xor_sync(0xffffffffu, mx1, 1));
        mx1 = fmaxf(mx1, __shfl_xor_sync(0xffffffffu, mx1, 2));
        float mn0 = fmaxf(m0, mx0), mn1 = fmaxf(m1, mx1);
        float corr0 = __expf(m0 - mn0), corr1 = __expf(m1 - mn1);
        m0 = mn0; m1 = mn1;
        float rs0 = 0.f, rs1 = 0.f;
#pragma unroll
        for (int nf = 0; nf < 8; nf++) {
            sacc[nf][0] = __expf(sacc[nf][0] - m0);
            sacc[nf][1] = __expf(sacc[nf][1] - m0);
            sacc[nf][2] = __expf(sacc[nf][2] - m1);
            sacc[nf][3] = __expf(sacc[nf][3] - m1);
            rs0 += sacc[nf][0] + sacc[nf][1];
            rs1 += sacc[nf][2] + sacc[nf][3];
        }
        rs0 += __shfl_xor_sync(0xffffffffu, rs0, 1);
        rs0 += __shfl_xor_sync(0xffffffffu, rs0, 2);
        rs1 += __shfl_xor_sync(0xffffffffu, rs1, 1);
        rs1 += __shfl_xor_sync(0xffffffffu, rs1, 2);
        l0 = l0 * corr0 + rs0;
        l1 = l1 * corr1 + rs1;
#pragma unroll
        for (int nf = 0; nf < 8; nf++) {
            oacc[nf][0] *= corr0; oacc[nf][1] *= corr0;
            oacc[nf][2] *= corr1; oacc[nf][3] *= corr1;
        }

        // ---- O += P V (hi/lo 3-product, P repacked from accumulators) ----
#pragma unroll
        for (int kc = 0; kc < 4; kc++) {
            uint32_t aph[4], apl[4];
            split2(sacc[2 * kc][0],     sacc[2 * kc][1],     aph[0], apl[0]);
            split2(sacc[2 * kc][2],     sacc[2 * kc][3],     aph[1], apl[1]);
            split2(sacc[2 * kc + 1][0], sacc[2 * kc + 1][1], aph[2], apl[2]);
            split2(sacc[2 * kc + 1][2], sacc[2 * kc + 1][3], aph[3], apl[3]);
            const uint32_t vrow = (uint32_t)(kc * 16 + (lane & 15));
#pragma unroll
            for (int nf = 0; nf < 8; nf++) {
                const uint32_t voff = (uint32_t)((vrow * FA_STR + nf * 8) * 2);
                uint32_t bvh[2], bvl[2];
                ldsm_x2t(bvh, uVh + voff);
                ldsm_x2t(bvl, uVl + voff);
                mma16816(oacc[nf], aph, bvh);
                mma16816(oacc[nf], aph, bvl);
                mma16816(oacc[nf], apl, bvh);
            }
        }
    }

    // ---- epilogue: normalize, split to bf16 hi/lo, store ----
    float inv0 = 1.f / l0, inv1 = 1.f / l1;
    const size_t goA = (qrow0 + wr + r0) * D_MODEL + (size_t)h * HEAD_D;
    const size_t goB = goA + 8 * D_MODEL;
#pragma unroll
    for (int nf = 0; nf < 8; nf++) {
        int d = nf * 8 + c0;
        uint32_t h0, lo0, h1, lo1;
        split2(oacc[nf][0] * inv0, oacc[nf][1] * inv0, h0, lo0);
        split2(oacc[nf][2] * inv1, oacc[nf][3] * inv1, h1, lo1);
        *(uint32_t*)(Oh_g + goA + d) = h0;
        *(uint32_t*)(Ol_g + goA + d) = lo0;
        *(uint32_t*)(Oh_g + goB + d) = h1;
        *(uint32_t*)(Ol_g + goB + d) = lo1;
    }
}

// ---------------------------------------------------------------------------
// kernel_launch: split(1) -> gemm_qkv(1) -> flash(1) -> gemm_o(1)
// ---------------------------------------------------------------------------
extern "C" void kernel_launch(void* const* d_in, const int* in_sizes, int n_in,
                              void* d_out, int out_size)
{
    const float* queries = (const float*)d_in[0];
    const float* keys    = (const float*)d_in[1];
    const float* values  = (const float*)d_in[2];
    const float* Wq = (const float*)d_in[3];
    const float* bq = (const float*)d_in[4];
    const float* Wk = (const float*)d_in[5];
    const float* bk = (const float*)d_in[6];
    const float* Wv = (const float*)d_in[7];
    const float* bv = (const float*)d_in[8];
    const float* Wo = (const float*)d_in[9];
    const float* bo = (const float*)d_in[10];
    float* out = (float*)d_out;

    __nv_bfloat16 *xh, *xl, *wh, *wl, *qh, *ql, *kh, *kl, *vh, *vl, *ah, *al;
    cudaGetSymbolAddress((void**)&xh, g_xh);
    cudaGetSymbolAddress((void**)&xl, g_xl);
    cudaGetSymbolAddress((void**)&wh, g_wh);
    cudaGetSymbolAddress((void**)&wl, g_wl);
    cudaGetSymbolAddress((void**)&qh, g_qh);
    cudaGetSymbolAddress((void**)&ql, g_ql);
    cudaGetSymbolAddress((void**)&kh, g_kh);
    cudaGetSymbolAddress((void**)&kl, g_kl);
    cudaGetSymbolAddress((void**)&vh, g_vh);
    cudaGetSymbolAddress((void**)&vl, g_vl);
    cudaGetSymbolAddress((void**)&ah, g_ah);
    cudaGetSymbolAddress((void**)&al, g_al);

    cudaFuncSetAttribute(flash_mma_kernel,
                         cudaFuncAttributeMaxDynamicSharedMemorySize, FA_SMEM);
    cudaFuncSetAttribute(gemm_qkv_kernel,
                         cudaFuncAttributeMaxDynamicSharedMemorySize, GSMEM);
    cudaFuncSetAttribute(gemm_o_kernel,
                         cudaFuncAttributeMaxDynamicSharedMemorySize, GSMEM);

    // 1) Fused split of all 7 tensors
    dim3 sGrd((unsigned)(XSZ / 4 / 256), 7);
    split_all_kernel<<<sGrd, 256>>>(queries, keys, values, Wq, Wk, Wv, Wo,
                                    xh, xl, wh, wl);

    // 2) Batched Q/K/V projections (z = tensor)
    dim3 gGrd(D_MODEL / 128, MTOT / 128, 3);   // (8, 32, 3)
    gemm_qkv_kernel<<<gGrd, 256, GSMEM>>>(xh, xl, wh, wl, bq, bk, bv,
                                          qh, ql, kh, kl, vh, vl);

    // 3) Attention (64-row Q tiles, heaviest CTAs first)
    dim3 aGrd(LSEQ / 64, N_HEADS, NB);         // (32, 16, 2)
    flash_mma_kernel<<<aGrd, 128, FA_SMEM>>>(qh, ql, kh, kl, vh, vl, ah, al);

    // 4) Output projection: fp32 out
    dim3 oGrd(D_MODEL / 128, MTOT / 128);      // (8, 32)
    gemm_o_kernel<<<oGrd, 256, GSMEM>>>(ah, al, wh + 3 * WSZ, wl + 3 * WSZ, bo, out);
}

// round 14
// speedup vs baseline: 1.8551x; 1.0531x over previous
#include <cuda_runtime.h>
#include <cuda_bf16.h>
#include <cuda_fp16.h>
#include <cstdint>
#include <math.h>

// Problem constants (fixed shapes from reference)
#define D_MODEL 1024
#define N_HEADS 16
#define HEAD_D  64
#define NB      2
#define LSEQ    2048
#define MTOT    (NB * LSEQ)   // 4096 rows total

#define XSZ ((size_t)MTOT * D_MODEL)     // 4M elements
#define WSZ ((size_t)D_MODEL * D_MODEL)  // 1M elements

// ---------------------------------------------------------------------------
// Scratch (allocation-free rule: __device__ globals)
// ---------------------------------------------------------------------------
__device__ __nv_bfloat16 g_xh[3][XSZ];   // q/k/v inputs hi
__device__ __nv_bfloat16 g_xl[3][XSZ];   // lo
__device__ __nv_bfloat16 g_wh[4][WSZ];   // Wq/Wk/Wv/Wo hi
__device__ __nv_bfloat16 g_wl[4][WSZ];   // lo
__device__ __nv_bfloat16 g_qh[XSZ];      // projected Q hi/lo (bf16)
__device__ __nv_bfloat16 g_ql[XSZ];
__device__ __nv_bfloat16 g_kh[XSZ];      // projected K hi/lo (bf16)
__device__ __nv_bfloat16 g_kl[XSZ];
__device__ __half        g_vh[XSZ];      // projected V hi/lo (fp16!)
__device__ __half        g_vl[XSZ];
__device__ __nv_bfloat16 g_ah[XSZ];      // attn out hi/lo (bf16)
__device__ __nv_bfloat16 g_al[XSZ];

// ---------------------------------------------------------------------------
// Small helpers
// ---------------------------------------------------------------------------
__device__ __forceinline__ uint32_t smem_u32(const void* p) {
    uint32_t a;
    asm("{ .reg .u64 t; cvta.to.shared.u64 t, %1; cvt.u32.u64 %0, t; }"
        : "=r"(a) : "l"(p));
    return a;
}
__device__ __forceinline__ void split2(float x, float y, uint32_t& hi, uint32_t& lo) {
    __nv_bfloat16 hx = __float2bfloat16_rn(x), hy = __float2bfloat16_rn(y);
    __nv_bfloat162 hp; hp.x = hx; hp.y = hy;
    hi = *reinterpret_cast<uint32_t*>(&hp);
    __nv_bfloat162 lp = __floats2bfloat162_rn(x - __bfloat162float(hx),
                                              y - __bfloat162float(hy));
    lo = *reinterpret_cast<uint32_t*>(&lp);
}
// fp16 variant (for V)
__device__ __forceinline__ void split2h(float x, float y, uint32_t& hi, uint32_t& lo) {
    __half hx = __float2half_rn(x), hy = __float2half_rn(y);
    __half2 hp; hp.x = hx; hp.y = hy;
    hi = *reinterpret_cast<uint32_t*>(&hp);
    __half2 lp = __floats2half2_rn(x - __half2float(hx), y - __half2float(hy));
    lo = *reinterpret_cast<uint32_t*>(&lp);
}
__device__ __forceinline__ uint32_t pack2h(float x, float y) {
    __half2 p = __floats2half2_rn(x, y);
    return *reinterpret_cast<uint32_t*>(&p);
}
__device__ __forceinline__ void mma16816(float* c, const uint32_t* a, const uint32_t* b) {
    asm volatile(
        "mma.sync.aligned.m16n8k16.row.col.f32.bf16.bf16.f32 "
        "{%0,%1,%2,%3}, {%4,%5,%6,%7}, {%8,%9}, {%0,%1,%2,%3};"
        : "+f"(c[0]), "+f"(c[1]), "+f"(c[2]), "+f"(c[3])
        : "r"(a[0]), "r"(a[1]), "r"(a[2]), "r"(a[3]), "r"(b[0]), "r"(b[1]));
}
__device__ __forceinline__ void mma16816h(float* c, const uint32_t* a, const uint32_t* b) {
    asm volatile(
        "mma.sync.aligned.m16n8k16.row.col.f32.f16.f16.f32 "
        "{%0,%1,%2,%3}, {%4,%5,%6,%7}, {%8,%9}, {%0,%1,%2,%3};"
        : "+f"(c[0]), "+f"(c[1]), "+f"(c[2]), "+f"(c[3])
        : "r"(a[0]), "r"(a[1]), "r"(a[2]), "r"(a[3]), "r"(b[0]), "r"(b[1]));
}
__device__ __forceinline__ void ldsm_x4(uint32_t* r, uint32_t a) {
    asm volatile("ldmatrix.sync.aligned.m8n8.x4.shared.b16 {%0,%1,%2,%3},[%4];"
                 : "=r"(r[0]), "=r"(r[1]), "=r"(r[2]), "=r"(r[3]) : "r"(a));
}
__device__ __forceinline__ void ldsm_x2(uint32_t* r, uint32_t a) {
    asm volatile("ldmatrix.sync.aligned.m8n8.x2.shared.b16 {%0,%1},[%2];"
                 : "=r"(r[0]), "=r"(r[1]) : "r"(a));
}
__device__ __forceinline__ void ldsm_x2t(uint32_t* r, uint32_t a) {
    asm volatile("ldmatrix.sync.aligned.m8n8.x2.trans.shared.b16 {%0,%1},[%2];"
                 : "=r"(r[0]), "=r"(r[1]) : "r"(a));
}
#define CP16(dst, src) \
    asm volatile("cp.async.cg.shared.global [%0], [%1], 16;" \
                 :: "r"(dst), "l"(src) : "memory")
#define CP_COMMIT() asm volatile("cp.async.commit_group;" ::: "memory")
#define CP_WAIT(n)  asm volatile("cp.async.wait_group %0;" :: "n"(n) : "memory")

// ---------------------------------------------------------------------------
// Fused fp32 -> bf16 hi/lo split, 4 float4 per thread (MLP=4, k-outer
// coalescing). blockIdx.y = tensor (0-2 inputs, 3-6 weights).
// ---------------------------------------------------------------------------
__global__ __launch_bounds__(256)
void split_all_kernel(const float* __restrict__ sx0, const float* __restrict__ sx1,
                      const float* __restrict__ sx2,
                      const float* __restrict__ sw0, const float* __restrict__ sw1,
                      const float* __restrict__ sw2, const float* __restrict__ sw3,
                      __nv_bfloat16* __restrict__ xh, __nv_bfloat16* __restrict__ xl,
                      __nv_bfloat16* __restrict__ wh, __nv_bfloat16* __restrict__ wl)
{
    const int t = blockIdx.y;
    const float* src;
    __nv_bfloat16 *hi, *lo;
    int n4;
    if (t < 3) {
        src = (t == 0) ? sx0 : (t == 1) ? sx1 : sx2;
        hi = xh + (size_t)t * XSZ;
        lo = xl + (size_t)t * XSZ;
        n4 = (int)(XSZ / 4);
    } else {
        int w = t - 3;
        src = (w == 0) ? sw0 : (w == 1) ? sw1 : (w == 2) ? sw2 : sw3;
        hi = wh + (size_t)w * WSZ;
        lo = wl + (size_t)w * WSZ;
        n4 = (int)(WSZ / 4);
    }
    const int base = blockIdx.x * 1024 + threadIdx.x;   // k-outer: +256 per k
    // Batch 4 independent loads (MLP=4), then convert + store.
    float4 v[4];
    bool ok[4];
#pragma unroll
    for (int k = 0; k < 4; k++) {
        int i = base + k * 256;
        ok[k] = (i < n4);
        if (ok[k]) v[k] = ((const float4*)src)[i];
    }
#pragma unroll
    for (int k = 0; k < 4; k++) {
        if (!ok[k]) continue;
        int i = base + k * 256;
        uint32_t h0, l0, h1, l1;
        split2(v[k].x, v[k].y, h0, l0);
        split2(v[k].z, v[k].w, h1, l1);
        ((uint2*)hi)[i] = make_uint2(h0, h1);
        ((uint2*)lo)[i] = make_uint2(l0, l1);
    }
}

// ---------------------------------------------------------------------------
// GEMM core — VERBATIM round-7/round-10 schedule (the proven-fast one).
// DO NOT modify compute_chunk or run(): four structurally different edits
// (R8/R9/R11/R12) each regressed 93us -> 214us with a spill-like signature.
// ---------------------------------------------------------------------------
#define ASTR 40                     // smem row stride (bf16), conflict-free
#define GARR (128 * ASTR)           // elements per array (10240 B)
#define GSTAGE (4 * GARR)           // Ah,Al,Bh,Bl per stage
#define GSMEM (2 * GSTAGE * 2)      // 81920 B total (2 stages)

struct GemmCore {
    uint32_t uAh[2], uAl[2], uBh[2], uBl[2];
    uint32_t stoff, aoff, boff;
    int lrow, lhalf, warp_m, warp_n, r0, c0;
    float acc[4][4][4];

    __device__ __forceinline__ void init(__nv_bfloat16* gsm, int tid) {
        const int lane = tid & 31;
        const int wid  = tid >> 5;
        warp_m = wid >> 2;
        warp_n = wid & 3;
        lrow  = tid >> 1;
        lhalf = (tid & 1) * 16;
        r0 = lane >> 2;
        c0 = (lane & 3) * 2;
        uint32_t uBase = smem_u32(gsm);
#pragma unroll
        for (int s = 0; s < 2; s++) {
            uint32_t sb = uBase + s * GSTAGE * 2;
            uAh[s] = sb;
            uAl[s] = sb + GARR * 2;
            uBh[s] = sb + 2 * GARR * 2;
            uBl[s] = sb + 3 * GARR * 2;
        }
        stoff = (uint32_t)(lrow * ASTR + lhalf) * 2;
        const int ja = lane >> 3, ra = lane & 7;
        aoff = (uint32_t)(((warp_m * 64 + (ja & 1) * 8 + ra) * ASTR + (ja >> 1) * 8) * 2);
        boff = (uint32_t)(((warp_n * 32 + (ja >> 1) * 8 + ra) * ASTR + (ja & 1) * 8) * 2);
#pragma unroll
        for (int mf = 0; mf < 4; mf++)
#pragma unroll
            for (int nf = 0; nf < 4; nf++)
#pragma unroll
                for (int r = 0; r < 4; r++) acc[mf][nf][r] = 0.f;
    }

    __device__ __forceinline__ void load_chunk(
        const __nv_bfloat16* Xh, const __nv_bfloat16* Xl,
        const __nv_bfloat16* Wh, const __nv_bfloat16* Wl,
        int bm, int bn, int ch, int s)
    {
        const int kofs = ch * 32;
        const size_t xoff = (size_t)(bm + lrow) * D_MODEL + kofs + lhalf;
        const size_t woff = (size_t)(bn + lrow) * D_MODEL + kofs + lhalf;
        CP16(uAh[s] + stoff,      Xh + xoff);
        CP16(uAh[s] + stoff + 16, Xh + xoff + 8);
        CP16(uAl[s] + stoff,      Xl + xoff);
        CP16(uAl[s] + stoff + 16, Xl + xoff + 8);
        CP16(uBh[s] + stoff,      Wh + woff);
        CP16(uBh[s] + stoff + 16, Wh + woff + 8);
        CP16(uBl[s] + stoff,      Wl + woff);
        CP16(uBl[s] + stoff + 16, Wl + woff + 8);
        CP_COMMIT();
    }

    __device__ __forceinline__ void compute_chunk(int s) {
#pragma unroll
        for (int kk = 0; kk < 32; kk += 16) {
            // B fragments: 2 x4 loads per (h,l) cover nf 0..3
            uint32_t bh[4][2], bl[4][2], t[4];
            ldsm_x4(t, uBh[s] + boff + kk * 2);
            bh[0][0] = t[0]; bh[0][1] = t[1]; bh[1][0] = t[2]; bh[1][1] = t[3];
            ldsm_x4(t, uBh[s] + boff + (16 * ASTR + kk) * 2);
            bh[2][0] = t[0]; bh[2][1] = t[1]; bh[3][0] = t[2]; bh[3][1] = t[3];
            ldsm_x4(t, uBl[s] + boff + kk * 2);
            bl[0][0] = t[0]; bl[0][1] = t[1]; bl[1][0] = t[2]; bl[1][1] = t[3];
            ldsm_x4(t, uBl[s] + boff + (16 * ASTR + kk) * 2);
            bl[2][0] = t[0]; bl[2][1] = t[1]; bl[3][0] = t[2]; bl[3][1] = t[3];

#pragma unroll
            for (int mf = 0; mf < 4; mf++) {
                uint32_t ah[4], al[4];
                ldsm_x4(ah, uAh[s] + aoff + (mf * 16 * ASTR + kk) * 2);
                ldsm_x4(al, uAl[s] + aoff + (mf * 16 * ASTR + kk) * 2);
#pragma unroll
                for (int nf = 0; nf < 4; nf++) {
                    mma16816(acc[mf][nf], ah, bh[nf]);
                    mma16816(acc[mf][nf], ah, bl[nf]);
                    mma16816(acc[mf][nf], al, bh[nf]);
                }
            }
        }
    }

    __device__ __forceinline__ void run(
        const __nv_bfloat16* Xh, const __nv_bfloat16* Xl,
        const __nv_bfloat16* Wh, const __nv_bfloat16* Wl, int bm, int bn)
    {
        load_chunk(Xh, Xl, Wh, Wl, bm, bn, 0, 0);
        const int NCH = D_MODEL / 32;   // 32
        for (int ch = 0; ch < NCH; ch++) {
            const int s = ch & 1;
            if (ch + 1 < NCH) {
                load_chunk(Xh, Xl, Wh, Wl, bm, bn, ch + 1, s ^ 1);
                CP_WAIT(1);
            } else {
                CP_WAIT(0);
            }
            __syncthreads();
            compute_chunk(s);
            __syncthreads();
        }
    }
};

// Batched QKV projection: blockIdx.z selects (input, weight, bias, output).
// t==2 (V) emits fp16 hi/lo; t<2 emit bf16 hi/lo. Stores are raw uint32.
__global__ __launch_bounds__(256, 2)
void gemm_qkv_kernel(const __nv_bfloat16* __restrict__ xh, const __nv_bfloat16* __restrict__ xl,
                     const __nv_bfloat16* __restrict__ wh, const __nv_bfloat16* __restrict__ wl,
                     const float* __restrict__ bq, const float* __restrict__ bk,
                     const float* __restrict__ bv,
                     __nv_bfloat16* __restrict__ qh, __nv_bfloat16* __restrict__ ql,
                     __nv_bfloat16* __restrict__ kh, __nv_bfloat16* __restrict__ kl,
                     __half* __restrict__ vh, __half* __restrict__ vl)
{
    extern __shared__ __nv_bfloat16 gsm[];
    const int t  = blockIdx.z;
    const int bm = blockIdx.y * 128;
    const int bn = blockIdx.x * 128;

    const __nv_bfloat16* Xh = xh + (size_t)t * XSZ;
    const __nv_bfloat16* Xl = xl + (size_t)t * XSZ;
    const __nv_bfloat16* Wh = wh + (size_t)t * WSZ;
    const __nv_bfloat16* Wl = wl + (size_t)t * WSZ;
    const float* bias = (t == 0) ? bq : (t == 1) ? bk : bv;
    uint16_t* Ch = (t == 0) ? (uint16_t*)qh : (t == 1) ? (uint16_t*)kh : (uint16_t*)vh;
    uint16_t* Cl = (t == 0) ? (uint16_t*)ql : (t == 1) ? (uint16_t*)kl : (uint16_t*)vl;

    GemmCore g;
    g.init(gsm, threadIdx.x);
    g.run(Xh, Xl, Wh, Wl, bm, bn);

    const bool fp16out = (t == 2);
#pragma unroll
    for (int mf = 0; mf < 4; mf++) {
        int row = bm + g.warp_m * 64 + mf * 16 + g.r0;
#pragma unroll
        for (int nf = 0; nf < 4; nf++) {
            int col = bn + g.warp_n * 32 + nf * 8 + g.c0;
            float2 bv2 = *(const float2*)(bias + col);
            float s00 = g.acc[mf][nf][0] + bv2.x;
            float s01 = g.acc[mf][nf][1] + bv2.y;
            float s10 = g.acc[mf][nf][2] + bv2.x;
            float s11 = g.acc[mf][nf][3] + bv2.y;
            uint32_t h0, l0, h1, l1;
            if (fp16out) {
                split2h(s00, s01, h0, l0);
                split2h(s10, s11, h1, l1);
            } else {
                split2(s00, s01, h0, l0);
                split2(s10, s11, h1, l1);
            }
            *(uint32_t*)(Ch + (size_t)row * D_MODEL + col)       = h0;
            *(uint32_t*)(Cl + (size_t)row * D_MODEL + col)       = l0;
            *(uint32_t*)(Ch + (size_t)(row + 8) * D_MODEL + col) = h1;
            *(uint32_t*)(Cl + (size_t)(row + 8) * D_MODEL + col) = l1;
        }
    }
}

// Output projection: fp32 out.
__global__ __launch_bounds__(256, 2)
void gemm_o_kernel(const __nv_bfloat16* __restrict__ Xh, const __nv_bfloat16* __restrict__ Xl,
                   const __nv_bfloat16* __restrict__ Wh, const __nv_bfloat16* __restrict__ Wl,
                   const float* __restrict__ bias, float* __restrict__ Cf)
{
    extern __shared__ __nv_bfloat16 gsm[];
    const int bm = blockIdx.y * 128;
    const int bn = blockIdx.x * 128;

    GemmCore g;
    g.init(gsm, threadIdx.x);
    g.run(Xh, Xl, Wh, Wl, bm, bn);

#pragma unroll
    for (int mf = 0; mf < 4; mf++) {
        int row = bm + g.warp_m * 64 + mf * 16 + g.r0;
#pragma unroll
        for (int nf = 0; nf < 4; nf++) {
            int col = bn + g.warp_n * 32 + nf * 8 + g.c0;
            float2 bv2 = *(const float2*)(bias + col);
            *(float2*)(Cf + (size_t)row * D_MODEL + col) =
                make_float2(g.acc[mf][nf][0] + bv2.x, g.acc[mf][nf][1] + bv2.y);
            *(float2*)(Cf + (size_t)(row + 8) * D_MODEL + col) =
                make_float2(g.acc[mf][nf][2] + bv2.x, g.acc[mf][nf][3] + bv2.y);
        }
    }
}

// ---------------------------------------------------------------------------
// Flash attention (causal), round-13 structure. QK: bf16 hi/lo 3-product.
// PV: P quantized to single fp16 (err 2^-11), V fp16 hi/lo -> 2-product.
// Descending qt order (heavy CTAs first).
// ---------------------------------------------------------------------------
#define FA_STR 72                   // [64][72] 16-bit tiles, conflict-free ldmatrix
#define FA_TILE (64 * FA_STR)       // elements per array
#define FT2 (FA_TILE * 2)           // bytes per array (9216)
#define FA_SMEM (10 * FT2)          // Q(2) + 2 stages x KV(4) = 92160 B

__global__ __launch_bounds__(128, 2)
void flash_mma_kernel(const __nv_bfloat16* __restrict__ Qh_g, const __nv_bfloat16* __restrict__ Ql_g,
                      const __nv_bfloat16* __restrict__ Kh_g, const __nv_bfloat16* __restrict__ Kl_g,
                      const __half* __restrict__ Vh_g, const __half* __restrict__ Vl_g,
                      __nv_bfloat16* __restrict__ Oh_g, __nv_bfloat16* __restrict__ Ol_g)
{
    extern __shared__ __nv_bfloat16 fsm[];
    __nv_bfloat16* sQh = fsm;
    __nv_bfloat16* sQl = fsm + FA_TILE;

    const int tid  = threadIdx.x;
    const int lane = tid & 31;
    const int wid  = tid >> 5;
    const int qt   = (int)(gridDim.x - 1 - blockIdx.x);   // descending work order
    const int h    = blockIdx.y;
    const int n    = blockIdx.z;

    const uint32_t uQh = smem_u32(sQh);
    const uint32_t uQl = smem_u32(sQl);
    const uint32_t uKV0 = uQh + 2 * FT2;   // stage 0 base

    const float scale = 0.125f;   // 1/sqrt(64)
    const int wr = wid * 16;      // warp's Q-row base within tile
    const int r0 = lane >> 2;     // 0..7
    const int c0 = (lane & 3) * 2;

    // Load Q tile (hi/lo), natural [row][d] layout (plain vector loads).
    const size_t qrow0 = (size_t)(n * LSEQ + qt * 64);
    const size_t gq = qrow0 * D_MODEL + (size_t)h * HEAD_D;
#pragma unroll
    for (int i = 0; i < 4; i++) {
        int f = tid + i * 128;          // 0..511
        int row = f >> 3, c8 = (f & 7) * 8;
        int so = row * FA_STR + c8;
        size_t go = gq + (size_t)row * D_MODEL + c8;
        *(uint4*)(sQh + so) = *(const uint4*)(Qh_g + go);
        *(uint4*)(sQl + so) = *(const uint4*)(Ql_g + go);
    }

    // K/V chunk loader via cp.async (16x16B per thread)
    auto load_kv = [&](int kt, int s) {
        const uint32_t base = uKV0 + (uint32_t)s * 4 * FT2;
        const size_t gk = ((size_t)(n * LSEQ + kt * 64)) * D_MODEL + (size_t)h * HEAD_D;
#pragma unroll
        for (int i = 0; i < 4; i++) {
            int f = tid + i * 128;
            int row = f >> 3, c8 = (f & 7) * 8;
            uint32_t so = (uint32_t)(row * FA_STR + c8) * 2;
            size_t go = gk + (size_t)row * D_MODEL + c8;
            CP16(base + so,           Kh_g + go);
            CP16(base + FT2 + so,     Kl_g + go);
            CP16(base + 2 * FT2 + so, Vh_g + go);
            CP16(base + 3 * FT2 + so, Vl_g + go);
        }
        CP_COMMIT();
    };

    float oacc[8][4];
#pragma unroll
    for (int nf = 0; nf < 8; nf++)
#pragma unroll
        for (int j = 0; j < 4; j++) oacc[nf][j] = 0.f;
    float m0 = -INFINITY, m1 = -INFINITY, l0 = 0.f, l1 = 0.f;

    load_kv(0, 0);

    for (int kt = 0; kt <= qt; kt++) {
        const int s = kt & 1;
        const uint32_t uKh = uKV0 + (uint32_t)s * 4 * FT2;
        const uint32_t uKl = uKh + FT2;
        const uint32_t uVh = uKh + 2 * FT2;
        const uint32_t uVl = uKh + 3 * FT2;

        CP_WAIT(0);        // current stage's copies arrived
        __syncthreads();   // all warps done with stage s^1 + copies visible
        if (kt < qt) load_kv(kt + 1, s ^ 1);   // prefetch overlaps compute below

        // ---- S = Q K^T (bf16 hi/lo 3-product) ----
        float sacc[8][4];
#pragma unroll
        for (int nf = 0; nf < 8; nf++)
#pragma unroll
            for (int j = 0; j < 4; j++) sacc[nf][j] = 0.f;

#pragma unroll
        for (int kc = 0; kc < 4; kc++) {
            const uint32_t aoff = (uint32_t)(((wr + (lane & 15)) * FA_STR
                                  + kc * 16 + (lane >> 4) * 8) * 2);
            uint32_t aqh[4], aql[4];
            ldsm_x4(aqh, uQh + aoff);
            ldsm_x4(aql, uQl + aoff);
            const uint32_t brow = (lane & 7);
            const uint32_t bk8  = ((lane >> 3) & 1) * 8;
#pragma unroll
            for (int nf = 0; nf < 8; nf++) {
                const uint32_t boff = (uint32_t)(((nf * 8 + brow) * FA_STR
                                      + kc * 16 + bk8) * 2);
                uint32_t bkh[2], bkl[2];
                ldsm_x2(bkh, uKh + boff);
                ldsm_x2(bkl, uKl + boff);
                mma16816(sacc[nf], aqh, bkh);
                mma16816(sacc[nf], aqh, bkl);
                mma16816(sacc[nf], aql, bkh);
            }
        }

        // ---- scale + causal mask ----
        if (kt == qt) {
#pragma unroll
            for (int nf = 0; nf < 8; nf++) {
                int col = nf * 8 + c0;
                int lrA = wr + r0, lrB = wr + r0 + 8;
                sacc[nf][0] = (col     > lrA) ? -INFINITY : sacc[nf][0] * scale;
                sacc[nf][1] = (col + 1 > lrA) ? -INFINITY : sacc[nf][1] * scale;
                sacc[nf][2] = (col     > lrB) ? -INFINITY : sacc[nf][2] * scale;
                sacc[nf][3] = (col + 1 > lrB) ? -INFINITY : sacc[nf][3] * scale;
            }
        } else {
#pragma unroll
            for (int nf = 0; nf < 8; nf++)
#pragma unroll
                for (int j = 0; j < 4; j++) sacc[nf][j] *= scale;
        }

        // ---- online softmax ----
        float mx0 = -INFINITY, mx1 = -INFINITY;
#pragma unroll
        for (int nf = 0; nf < 8; nf++) {
            mx0 = fmaxf(mx0, fmaxf(sacc[nf][0], sacc[nf][1]));
            mx1 = fmaxf(mx1, fmaxf(sacc[nf][2], sacc[nf][3]));
        }
        mx0 = fmaxf(mx0, __shfl_xor_sync(0xffffffffu, mx0, 1));
        mx0 = fmaxf(mx0, __shfl_xor_sync(0xffffffffu, mx0, 2));
        mx1 = fmaxf(mx1, __shfl_xor_sync(0xffffffffu, mx1, 1));
        mx1 = fmaxf(mx1, __shfl_xor_sync(0xffffffffu, mx1, 2));
        float mn0 = fmaxf(m0, mx0), mn1 = fmaxf(m1, mx1);
        float corr0 = __expf(m0 - mn0), corr1 = __expf(m1 - mn1);
        m0 = mn0; m1 = mn1;
        float rs0 = 0.f, rs1 = 0.f;
#pragma unroll
        for (int nf = 0; nf < 8; nf++) {
            sacc[nf][0] = __expf(sacc[nf][0] - m0);
            sacc[nf][1] = __expf(sacc[nf][1] - m0);
            sacc[nf][2] = __expf(sacc[nf][2] - m1);
            sacc[nf][3] = __expf(sacc[nf][3] - m1);
            rs0 += sacc[nf][0] + sacc[nf][1];
            rs1 += sacc[nf][2] + sacc[nf][3];
        }
        rs0 += __shfl_xor_sync(0xffffffffu, rs0, 1);
        rs0 += __shfl_xor_sync(0xffffffffu, rs0, 2);
        rs1 += __shfl_xor_sync(0xffffffffu, rs1, 1);
        rs1 += __shfl_xor_sync(0xffffffffu, rs1, 2);
        l0 = l0 * corr0 + rs0;
        l1 = l1 * corr1 + rs1;
#pragma unroll
        for (int nf = 0; nf < 8; nf++) {
            oacc[nf][0] *= corr0; oacc[nf][1] *= corr0;
            oacc[nf][2] *= corr1; oacc[nf][3] *= corr1;
        }

        // ---- O += P V : P single fp16, V fp16 hi/lo (2-product) ----
#pragma unroll
        for (int kc = 0; kc < 4; kc++) {
            uint32_t apf[4];
            apf[0] = pack2h(sacc[2 * kc][0],     sacc[2 * kc][1]);
            apf[1] = pack2h(sacc[2 * kc][2],     sacc[2 * kc][3]);
            apf[2] = pack2h(sacc[2 * kc + 1][0], sacc[2 * kc + 1][1]);
            apf[3] = pack2h(sacc[2 * kc + 1][2], sacc[2 * kc + 1][3]);
            const uint32_t vrow = (uint32_t)(kc * 16 + (lane & 15));
#pragma unroll
            for (int nf = 0; nf < 8; nf++) {
                const uint32_t voff = (uint32_t)((vrow * FA_STR + nf * 8) * 2);
                uint32_t bvh[2], bvl[2];
                ldsm_x2t(bvh, uVh + voff);
                ldsm_x2t(bvl, uVl + voff);
                mma16816h(oacc[nf], apf, bvh);
                mma16816h(oacc[nf], apf, bvl);
            }
        }
    }

    // ---- epilogue: normalize, split to bf16 hi/lo, store ----
    float inv0 = 1.f / l0, inv1 = 1.f / l1;
    const size_t goA = (qrow0 + wr + r0) * D_MODEL + (size_t)h * HEAD_D;
    const size_t goB = goA + 8 * D_MODEL;
#pragma unroll
    for (int nf = 0; nf < 8; nf++) {
        int d = nf * 8 + c0;
        uint32_t h0, lo0, h1, lo1;
        split2(oacc[nf][0] * inv0, oacc[nf][1] * inv0, h0, lo0);
        split2(oacc[nf][2] * inv1, oacc[nf][3] * inv1, h1, lo1);
        *(uint32_t*)(Oh_g + goA + d) = h0;
        *(uint32_t*)(Ol_g + goA + d) = lo0;
        *(uint32_t*)(Oh_g + goB + d) = h1;
        *(uint32_t*)(Ol_g + goB + d) = lo1;
    }
}

// ---------------------------------------------------------------------------
// kernel_launch: split(1) -> gemm_qkv(1) -> flash(1) -> gemm_o(1)
// ---------------------------------------------------------------------------
extern "C" void kernel_launch(void* const* d_in, const int* in_sizes, int n_in,
                              void* d_out, int out_size)
{
    const float* queries = (const float*)d_in[0];
    const float* keys    = (const float*)d_in[1];
    const float* values  = (const float*)d_in[2];
    const float* Wq = (const float*)d_in[3];
    const float* bq = (const float*)d_in[4];
    const float* Wk = (const float*)d_in[5];
    const float* bk = (const float*)d_in[6];
    const float* Wv = (const float*)d_in[7];
    const float* bv = (const float*)d_in[8];
    const float* Wo = (const float*)d_in[9];
    const float* bo = (const float*)d_in[10];
    float* out = (float*)d_out;

    __nv_bfloat16 *xh, *xl, *wh, *wl, *qh, *ql, *kh, *kl, *ah, *al;
    __half *vh, *vl;
    cudaGetSymbolAddress((void**)&xh, g_xh);
    cudaGetSymbolAddress((void**)&xl, g_xl);
    cudaGetSymbolAddress((void**)&wh, g_wh);
    cudaGetSymbolAddress((void**)&wl, g_wl);
    cudaGetSymbolAddress((void**)&qh, g_qh);
    cudaGetSymbolAddress((void**)&ql, g_ql);
    cudaGetSymbolAddress((void**)&kh, g_kh);
    cudaGetSymbolAddress((void**)&kl, g_kl);
    cudaGetSymbolAddress((void**)&vh, g_vh);
    cudaGetSymbolAddress((void**)&vl, g_vl);
    cudaGetSymbolAddress((void**)&ah, g_ah);
    cudaGetSymbolAddress((void**)&al, g_al);

    cudaFuncSetAttribute(flash_mma_kernel,
                         cudaFuncAttributeMaxDynamicSharedMemorySize, FA_SMEM);
    cudaFuncSetAttribute(gemm_qkv_kernel,
                         cudaFuncAttributeMaxDynamicSharedMemorySize, GSMEM);
    cudaFuncSetAttribute(gemm_o_kernel,
                         cudaFuncAttributeMaxDynamicSharedMemorySize, GSMEM);

    // 1) Fused split of all 7 tensors (4 float4 per thread)
    dim3 sGrd((unsigned)(XSZ / 4 / 1024), 7);
    split_all_kernel<<<sGrd, 256>>>(queries, keys, values, Wq, Wk, Wv, Wo,
                                    xh, xl, wh, wl);

    // 2) Batched Q/K/V projections (z = tensor; V emits fp16 hi/lo)
    dim3 gGrd(D_MODEL / 128, MTOT / 128, 3);   // (8, 32, 3)
    gemm_qkv_kernel<<<gGrd, 256, GSMEM>>>(xh, xl, wh, wl, bq, bk, bv,
                                          qh, ql, kh, kl, vh, vl);

    // 3) Attention (64-row Q tiles, heaviest CTAs first)
    dim3 aGrd(LSEQ / 64, N_HEADS, NB);         // (32, 16, 2)
    flash_mma_kernel<<<aGrd, 128, FA_SMEM>>>(qh, ql, kh, kl, vh, vl, ah, al);

    // 4) Output projection: fp32 out
    dim3 oGrd(D_MODEL / 128, MTOT / 128);      // (8, 32)
    gemm_o_kernel<<<oGrd, 256, GSMEM>>>(ah, al, wh + 3 * WSZ, wl + 3 * WSZ, bo, out);
}

// round 15
// speedup vs baseline: 1.9649x; 1.0592x over previous
#include <cuda_runtime.h>
#include <cuda_bf16.h>
#include <cuda_fp16.h>
#include <cstdint>
#include <math.h>

// Problem constants (fixed shapes from reference)
#define D_MODEL 1024
#define N_HEADS 16
#define HEAD_D  64
#define NB      2
#define LSEQ    2048
#define MTOT    (NB * LSEQ)   // 4096 rows total

#define XSZ ((size_t)MTOT * D_MODEL)     // 4M elements
#define WSZ ((size_t)D_MODEL * D_MODEL)  // 1M elements

// ---------------------------------------------------------------------------
// Scratch (allocation-free rule: __device__ globals)
// ---------------------------------------------------------------------------
__device__ __nv_bfloat16 g_xh[3][XSZ];   // q/k/v inputs hi (bf16)
__device__ __nv_bfloat16 g_xl[3][XSZ];   // lo
__device__ __nv_bfloat16 g_wh[4][WSZ];   // Wq/Wk/Wv/Wo hi (bf16)
__device__ __nv_bfloat16 g_wl[4][WSZ];   // lo
__device__ __half        g_qf[XSZ];      // projected Q, single fp16, pre-scaled by 1/8
__device__ __half        g_kh[XSZ];      // projected K hi/lo (fp16)
__device__ __half        g_kl[XSZ];
__device__ __half        g_vh[XSZ];      // projected V hi/lo (fp16)
__device__ __half        g_vl[XSZ];
__device__ __nv_bfloat16 g_ah[XSZ];      // attn out hi/lo (bf16)
__device__ __nv_bfloat16 g_al[XSZ];

// ---------------------------------------------------------------------------
// Small helpers
// ---------------------------------------------------------------------------
__device__ __forceinline__ uint32_t smem_u32(const void* p) {
    uint32_t a;
    asm("{ .reg .u64 t; cvta.to.shared.u64 t, %1; cvt.u32.u64 %0, t; }"
        : "=r"(a) : "l"(p));
    return a;
}
__device__ __forceinline__ void split2(float x, float y, uint32_t& hi, uint32_t& lo) {
    __nv_bfloat16 hx = __float2bfloat16_rn(x), hy = __float2bfloat16_rn(y);
    __nv_bfloat162 hp; hp.x = hx; hp.y = hy;
    hi = *reinterpret_cast<uint32_t*>(&hp);
    __nv_bfloat162 lp = __floats2bfloat162_rn(x - __bfloat162float(hx),
                                              y - __bfloat162float(hy));
    lo = *reinterpret_cast<uint32_t*>(&lp);
}
// fp16 variant (for K and V)
__device__ __forceinline__ void split2h(float x, float y, uint32_t& hi, uint32_t& lo) {
    __half hx = __float2half_rn(x), hy = __float2half_rn(y);
    __half2 hp; hp.x = hx; hp.y = hy;
    hi = *reinterpret_cast<uint32_t*>(&hp);
    __half2 lp = __floats2half2_rn(x - __half2float(hx), y - __half2float(hy));
    lo = *reinterpret_cast<uint32_t*>(&lp);
}
__device__ __forceinline__ uint32_t pack2h(float x, float y) {
    __half2 p = __floats2half2_rn(x, y);
    return *reinterpret_cast<uint32_t*>(&p);
}
__device__ __forceinline__ void mma16816(float* c, const uint32_t* a, const uint32_t* b) {
    asm volatile(
        "mma.sync.aligned.m16n8k16.row.col.f32.bf16.bf16.f32 "
        "{%0,%1,%2,%3}, {%4,%5,%6,%7}, {%8,%9}, {%0,%1,%2,%3};"
        : "+f"(c[0]), "+f"(c[1]), "+f"(c[2]), "+f"(c[3])
        : "r"(a[0]), "r"(a[1]), "r"(a[2]), "r"(a[3]), "r"(b[0]), "r"(b[1]));
}
__device__ __forceinline__ void mma16816h(float* c, const uint32_t* a, const uint32_t* b) {
    asm volatile(
        "mma.sync.aligned.m16n8k16.row.col.f32.f16.f16.f32 "
        "{%0,%1,%2,%3}, {%4,%5,%6,%7}, {%8,%9}, {%0,%1,%2,%3};"
        : "+f"(c[0]), "+f"(c[1]), "+f"(c[2]), "+f"(c[3])
        : "r"(a[0]), "r"(a[1]), "r"(a[2]), "r"(a[3]), "r"(b[0]), "r"(b[1]));
}
__device__ __forceinline__ void ldsm_x4(uint32_t* r, uint32_t a) {
    asm volatile("ldmatrix.sync.aligned.m8n8.x4.shared.b16 {%0,%1,%2,%3},[%4];"
                 : "=r"(r[0]), "=r"(r[1]), "=r"(r[2]), "=r"(r[3]) : "r"(a));
}
__device__ __forceinline__ void ldsm_x2(uint32_t* r, uint32_t a) {
    asm volatile("ldmatrix.sync.aligned.m8n8.x2.shared.b16 {%0,%1},[%2];"
                 : "=r"(r[0]), "=r"(r[1]) : "r"(a));
}
__device__ __forceinline__ void ldsm_x2t(uint32_t* r, uint32_t a) {
    asm volatile("ldmatrix.sync.aligned.m8n8.x2.trans.shared.b16 {%0,%1},[%2];"
                 : "=r"(r[0]), "=r"(r[1]) : "r"(a));
}
#define CP16(dst, src) \
    asm volatile("cp.async.cg.shared.global [%0], [%1], 16;" \
                 :: "r"(dst), "l"(src) : "memory")
#define CP_COMMIT() asm volatile("cp.async.commit_group;" ::: "memory")
#define CP_WAIT(n)  asm volatile("cp.async.wait_group %0;" :: "n"(n) : "memory")

// ---------------------------------------------------------------------------
// Fused fp32 -> bf16 hi/lo split, 4 float4 per thread (MLP=4).
// blockIdx.y = tensor (0-2 inputs, 3-6 weights).
// ---------------------------------------------------------------------------
__global__ __launch_bounds__(256)
void split_all_kernel(const float* __restrict__ sx0, const float* __restrict__ sx1,
                      const float* __restrict__ sx2,
                      const float* __restrict__ sw0, const float* __restrict__ sw1,
                      const float* __restrict__ sw2, const float* __restrict__ sw3,
                      __nv_bfloat16* __restrict__ xh, __nv_bfloat16* __restrict__ xl,
                      __nv_bfloat16* __restrict__ wh, __nv_bfloat16* __restrict__ wl)
{
    const int t = blockIdx.y;
    const float* src;
    __nv_bfloat16 *hi, *lo;
    int n4;
    if (t < 3) {
        src = (t == 0) ? sx0 : (t == 1) ? sx1 : sx2;
        hi = xh + (size_t)t * XSZ;
        lo = xl + (size_t)t * XSZ;
        n4 = (int)(XSZ / 4);
    } else {
        int w = t - 3;
        src = (w == 0) ? sw0 : (w == 1) ? sw1 : (w == 2) ? sw2 : sw3;
        hi = wh + (size_t)w * WSZ;
        lo = wl + (size_t)w * WSZ;
        n4 = (int)(WSZ / 4);
    }
    const int base = blockIdx.x * 1024 + threadIdx.x;
    float4 v[4];
    bool ok[4];
#pragma unroll
    for (int k = 0; k < 4; k++) {
        int i = base + k * 256;
        ok[k] = (i < n4);
        if (ok[k]) v[k] = ((const float4*)src)[i];
    }
#pragma unroll
    for (int k = 0; k < 4; k++) {
        if (!ok[k]) continue;
        int i = base + k * 256;
        uint32_t h0, l0, h1, l1;
        split2(v[k].x, v[k].y, h0, l0);
        split2(v[k].z, v[k].w, h1, l1);
        ((uint2*)hi)[i] = make_uint2(h0, h1);
        ((uint2*)lo)[i] = make_uint2(l0, l1);
    }
}

// ---------------------------------------------------------------------------
// GEMM core — VERBATIM round-7/round-10 schedule (the proven-fast one).
// DO NOT modify compute_chunk or run(): four structurally different edits
// (R8/R9/R11/R12) each regressed 93us -> 214us with a spill-like signature.
// ---------------------------------------------------------------------------
#define ASTR 40                     // smem row stride (bf16), conflict-free
#define GARR (128 * ASTR)           // elements per array (10240 B)
#define GSTAGE (4 * GARR)           // Ah,Al,Bh,Bl per stage
#define GSMEM (2 * GSTAGE * 2)      // 81920 B total (2 stages)

struct GemmCore {
    uint32_t uAh[2], uAl[2], uBh[2], uBl[2];
    uint32_t stoff, aoff, boff;
    int lrow, lhalf, warp_m, warp_n, r0, c0;
    float acc[4][4][4];

    __device__ __forceinline__ void init(__nv_bfloat16* gsm, int tid) {
        const int lane = tid & 31;
        const int wid  = tid >> 5;
        warp_m = wid >> 2;
        warp_n = wid & 3;
        lrow  = tid >> 1;
        lhalf = (tid & 1) * 16;
        r0 = lane >> 2;
        c0 = (lane & 3) * 2;
        uint32_t uBase = smem_u32(gsm);
#pragma unroll
        for (int s = 0; s < 2; s++) {
            uint32_t sb = uBase + s * GSTAGE * 2;
            uAh[s] = sb;
            uAl[s] = sb + GARR * 2;
            uBh[s] = sb + 2 * GARR * 2;
            uBl[s] = sb + 3 * GARR * 2;
        }
        stoff = (uint32_t)(lrow * ASTR + lhalf) * 2;
        const int ja = lane >> 3, ra = lane & 7;
        aoff = (uint32_t)(((warp_m * 64 + (ja & 1) * 8 + ra) * ASTR + (ja >> 1) * 8) * 2);
        boff = (uint32_t)(((warp_n * 32 + (ja >> 1) * 8 + ra) * ASTR + (ja & 1) * 8) * 2);
#pragma unroll
        for (int mf = 0; mf < 4; mf++)
#pragma unroll
            for (int nf = 0; nf < 4; nf++)
#pragma unroll
                for (int r = 0; r < 4; r++) acc[mf][nf][r] = 0.f;
    }

    __device__ __forceinline__ void load_chunk(
        const __nv_bfloat16* Xh, const __nv_bfloat16* Xl,
        const __nv_bfloat16* Wh, const __nv_bfloat16* Wl,
        int bm, int bn, int ch, int s)
    {
        const int kofs = ch * 32;
        const size_t xoff = (size_t)(bm + lrow) * D_MODEL + kofs + lhalf;
        const size_t woff = (size_t)(bn + lrow) * D_MODEL + kofs + lhalf;
        CP16(uAh[s] + stoff,      Xh + xoff);
        CP16(uAh[s] + stoff + 16, Xh + xoff + 8);
        CP16(uAl[s] + stoff,      Xl + xoff);
        CP16(uAl[s] + stoff + 16, Xl + xoff + 8);
        CP16(uBh[s] + stoff,      Wh + woff);
        CP16(uBh[s] + stoff + 16, Wh + woff + 8);
        CP16(uBl[s] + stoff,      Wl + woff);
        CP16(uBl[s] + stoff + 16, Wl + woff + 8);
        CP_COMMIT();
    }

    __device__ __forceinline__ void compute_chunk(int s) {
#pragma unroll
        for (int kk = 0; kk < 32; kk += 16) {
            uint32_t bh[4][2], bl[4][2], t[4];
            ldsm_x4(t, uBh[s] + boff + kk * 2);
            bh[0][0] = t[0]; bh[0][1] = t[1]; bh[1][0] = t[2]; bh[1][1] = t[3];
            ldsm_x4(t, uBh[s] + boff + (16 * ASTR + kk) * 2);
            bh[2][0] = t[0]; bh[2][1] = t[1]; bh[3][0] = t[2]; bh[3][1] = t[3];
            ldsm_x4(t, uBl[s] + boff + kk * 2);
            bl[0][0] = t[0]; bl[0][1] = t[1]; bl[1][0] = t[2]; bl[1][1] = t[3];
            ldsm_x4(t, uBl[s] + boff + (16 * ASTR + kk) * 2);
            bl[2][0] = t[0]; bl[2][1] = t[1]; bl[3][0] = t[2]; bl[3][1] = t[3];

#pragma unroll
            for (int mf = 0; mf < 4; mf++) {
                uint32_t ah[4], al[4];
                ldsm_x4(ah, uAh[s] + aoff + (mf * 16 * ASTR + kk) * 2);
                ldsm_x4(al, uAl[s] + aoff + (mf * 16 * ASTR + kk) * 2);
#pragma unroll
                for (int nf = 0; nf < 4; nf++) {
                    mma16816(acc[mf][nf], ah, bh[nf]);
                    mma16816(acc[mf][nf], ah, bl[nf]);
                    mma16816(acc[mf][nf], al, bh[nf]);
                }
            }
        }
    }

    __device__ __forceinline__ void run(
        const __nv_bfloat16* Xh, const __nv_bfloat16* Xl,
        const __nv_bfloat16* Wh, const __nv_bfloat16* Wl, int bm, int bn)
    {
        load_chunk(Xh, Xl, Wh, Wl, bm, bn, 0, 0);
        const int NCH = D_MODEL / 32;   // 32
        for (int ch = 0; ch < NCH; ch++) {
            const int s = ch & 1;
            if (ch + 1 < NCH) {
                load_chunk(Xh, Xl, Wh, Wl, bm, bn, ch + 1, s ^ 1);
                CP_WAIT(1);
            } else {
                CP_WAIT(0);
            }
            __syncthreads();
            compute_chunk(s);
            __syncthreads();
        }
    }
};

// Batched QKV projection: blockIdx.z selects (input, weight, bias, output).
// t==0 (Q): single fp16, pre-scaled by 1/8.  t==1 (K), t==2 (V): fp16 hi/lo.
__global__ __launch_bounds__(256, 2)
void gemm_qkv_kernel(const __nv_bfloat16* __restrict__ xh, const __nv_bfloat16* __restrict__ xl,
                     const __nv_bfloat16* __restrict__ wh, const __nv_bfloat16* __restrict__ wl,
                     const float* __restrict__ bq, const float* __restrict__ bk,
                     const float* __restrict__ bv,
                     __half* __restrict__ qf,
                     __half* __restrict__ kh, __half* __restrict__ kl,
                     __half* __restrict__ vh, __half* __restrict__ vl)
{
    extern __shared__ __nv_bfloat16 gsm[];
    const int t  = blockIdx.z;
    const int bm = blockIdx.y * 128;
    const int bn = blockIdx.x * 128;

    const __nv_bfloat16* Xh = xh + (size_t)t * XSZ;
    const __nv_bfloat16* Xl = xl + (size_t)t * XSZ;
    const __nv_bfloat16* Wh = wh + (size_t)t * WSZ;
    const __nv_bfloat16* Wl = wl + (size_t)t * WSZ;
    const float* bias = (t == 0) ? bq : (t == 1) ? bk : bv;
    uint16_t* Ch = (t == 0) ? (uint16_t*)qf : (t == 1) ? (uint16_t*)kh : (uint16_t*)vh;
    uint16_t* Cl = (t == 1) ? (uint16_t*)kl : (uint16_t*)vl;   // unused for t==0

    GemmCore g;
    g.init(gsm, threadIdx.x);
    g.run(Xh, Xl, Wh, Wl, bm, bn);

#pragma unroll
    for (int mf = 0; mf < 4; mf++) {
        int row = bm + g.warp_m * 64 + mf * 16 + g.r0;
#pragma unroll
        for (int nf = 0; nf < 4; nf++) {
            int col = bn + g.warp_n * 32 + nf * 8 + g.c0;
            float2 bv2 = *(const float2*)(bias + col);
            float s00 = g.acc[mf][nf][0] + bv2.x;
            float s01 = g.acc[mf][nf][1] + bv2.y;
            float s10 = g.acc[mf][nf][2] + bv2.x;
            float s11 = g.acc[mf][nf][3] + bv2.y;
            if (t == 0) {
                // Q: fold in 1/sqrt(64), single fp16
                *(uint32_t*)(Ch + (size_t)row * D_MODEL + col) =
                    pack2h(s00 * 0.125f, s01 * 0.125f);
                *(uint32_t*)(Ch + (size_t)(row + 8) * D_MODEL + col) =
                    pack2h(s10 * 0.125f, s11 * 0.125f);
            } else {
                uint32_t h0, l0, h1, l1;
                split2h(s00, s01, h0, l0);
                split2h(s10, s11, h1, l1);
                *(uint32_t*)(Ch + (size_t)row * D_MODEL + col)       = h0;
                *(uint32_t*)(Cl + (size_t)row * D_MODEL + col)       = l0;
                *(uint32_t*)(Ch + (size_t)(row + 8) * D_MODEL + col) = h1;
                *(uint32_t*)(Cl + (size_t)(row + 8) * D_MODEL + col) = l1;
            }
        }
    }
}

// Output projection: fp32 out.
__global__ __launch_bounds__(256, 2)
void gemm_o_kernel(const __nv_bfloat16* __restrict__ Xh, const __nv_bfloat16* __restrict__ Xl,
                   const __nv_bfloat16* __restrict__ Wh, const __nv_bfloat16* __restrict__ Wl,
                   const float* __restrict__ bias, float* __restrict__ Cf)
{
    extern __shared__ __nv_bfloat16 gsm[];
    const int bm = blockIdx.y * 128;
    const int bn = blockIdx.x * 128;

    GemmCore g;
    g.init(gsm, threadIdx.x);
    g.run(Xh, Xl, Wh, Wl, bm, bn);

#pragma unroll
    for (int mf = 0; mf < 4; mf++) {
        int row = bm + g.warp_m * 64 + mf * 16 + g.r0;
#pragma unroll
        for (int nf = 0; nf < 4; nf++) {
            int col = bn + g.warp_n * 32 + nf * 8 + g.c0;
            float2 bv2 = *(const float2*)(bias + col);
            *(float2*)(Cf + (size_t)row * D_MODEL + col) =
                make_float2(g.acc[mf][nf][0] + bv2.x, g.acc[mf][nf][1] + bv2.y);
            *(float2*)(Cf + (size_t)(row + 8) * D_MODEL + col) =
                make_float2(g.acc[mf][nf][2] + bv2.x, g.acc[mf][nf][3] + bv2.y);
        }
    }
}

// ---------------------------------------------------------------------------
// Flash attention (causal). QK: Qf(fp16, pre-scaled) x K fp16 hi/lo -> 2 MMAs.
// PV: P single fp16 x V fp16 hi/lo -> 2 MMAs. Descending qt order.
// ---------------------------------------------------------------------------
#define FA_STR 72                   // [64][72] 16-bit tiles, conflict-free ldmatrix
#define FA_TILE (64 * FA_STR)       // elements per array
#define FT2 (FA_TILE * 2)           // bytes per array (9216)
#define FA_SMEM (9 * FT2)           // Q(1) + 2 stages x KV(4) = 82944 B

__global__ __launch_bounds__(128, 2)
void flash_mma_kernel(const __half* __restrict__ Qf_g,
                      const __half* __restrict__ Kh_g, const __half* __restrict__ Kl_g,
                      const __half* __restrict__ Vh_g, const __half* __restrict__ Vl_g,
                      __nv_bfloat16* __restrict__ Oh_g, __nv_bfloat16* __restrict__ Ol_g)
{
    extern __shared__ __half fsmh[];
    __half* sQf = fsmh;

    const int tid  = threadIdx.x;
    const int lane = tid & 31;
    const int wid  = tid >> 5;
    const int qt   = (int)(gridDim.x - 1 - blockIdx.x);   // descending work order
    const int h    = blockIdx.y;
    const int n    = blockIdx.z;

    const uint32_t uQf = smem_u32(sQf);
    const uint32_t uKV0 = uQf + FT2;   // stage 0 base

    const int wr = wid * 16;      // warp's Q-row base within tile
    const int r0 = lane >> 2;     // 0..7
    const int c0 = (lane & 3) * 2;

    // Load Q tile (single fp16), natural [row][d] layout.
    const size_t qrow0 = (size_t)(n * LSEQ + qt * 64);
    const size_t gq = qrow0 * D_MODEL + (size_t)h * HEAD_D;
#pragma unroll
    for (int i = 0; i < 4; i++) {
        int f = tid + i * 128;          // 0..511
        int row = f >> 3, c8 = (f & 7) * 8;
        *(uint4*)(sQf + row * FA_STR + c8) =
            *(const uint4*)(Qf_g + gq + (size_t)row * D_MODEL + c8);
    }

    // K/V chunk loader via cp.async (16x16B per thread)
    auto load_kv = [&](int kt, int s) {
        const uint32_t base = uKV0 + (uint32_t)s * 4 * FT2;
        const size_t gk = ((size_t)(n * LSEQ + kt * 64)) * D_MODEL + (size_t)h * HEAD_D;
#pragma unroll
        for (int i = 0; i < 4; i++) {
            int f = tid + i * 128;
            int row = f >> 3, c8 = (f & 7) * 8;
            uint32_t so = (uint32_t)(row * FA_STR + c8) * 2;
            size_t go = gk + (size_t)row * D_MODEL + c8;
            CP16(base + so,           Kh_g + go);
            CP16(base + FT2 + so,     Kl_g + go);
            CP16(base + 2 * FT2 + so, Vh_g + go);
            CP16(base + 3 * FT2 + so, Vl_g + go);
        }
        CP_COMMIT();
    };

    float oacc[8][4];
#pragma unroll
    for (int nf = 0; nf < 8; nf++)
#pragma unroll
        for (int j = 0; j < 4; j++) oacc[nf][j] = 0.f;
    float m0 = -INFINITY, m1 = -INFINITY, l0 = 0.f, l1 = 0.f;

    load_kv(0, 0);

    for (int kt = 0; kt <= qt; kt++) {
        const int s = kt & 1;
        const uint32_t uKh = uKV0 + (uint32_t)s * 4 * FT2;
        const uint32_t uKl = uKh + FT2;
        const uint32_t uVh = uKh + 2 * FT2;
        const uint32_t uVl = uKh + 3 * FT2;

        CP_WAIT(0);        // current stage's copies arrived
        __syncthreads();   // all warps done with stage s^1 + copies visible
        if (kt < qt) load_kv(kt + 1, s ^ 1);   // prefetch overlaps compute below

        // ---- S = Qf K^T (fp16, 2-product: Qf*Kh + Qf*Kl) ----
        float sacc[8][4];
#pragma unroll
        for (int nf = 0; nf < 8; nf++)
#pragma unroll
            for (int j = 0; j < 4; j++) sacc[nf][j] = 0.f;

#pragma unroll
        for (int kc = 0; kc < 4; kc++) {
            const uint32_t aoff = (uint32_t)(((wr + (lane & 15)) * FA_STR
                                  + kc * 16 + (lane >> 4) * 8) * 2);
            uint32_t aqf[4];
            ldsm_x4(aqf, uQf + aoff);
            const uint32_t brow = (lane & 7);
            const uint32_t bk8  = ((lane >> 3) & 1) * 8;
#pragma unroll
            for (int nf = 0; nf < 8; nf++) {
                const uint32_t boff = (uint32_t)(((nf * 8 + brow) * FA_STR
                                      + kc * 16 + bk8) * 2);
                uint32_t bkh[2], bkl[2];
                ldsm_x2(bkh, uKh + boff);
                ldsm_x2(bkl, uKl + boff);
                mma16816h(sacc[nf], aqf, bkh);
                mma16816h(sacc[nf], aqf, bkl);
            }
        }

        // ---- causal mask (scale already folded into Q) ----
        if (kt == qt) {
#pragma unroll
            for (int nf = 0; nf < 8; nf++) {
                int col = nf * 8 + c0;
                int lrA = wr + r0, lrB = wr + r0 + 8;
                if (col     > lrA) sacc[nf][0] = -INFINITY;
                if (col + 1 > lrA) sacc[nf][1] = -INFINITY;
                if (col     > lrB) sacc[nf][2] = -INFINITY;
                if (col + 1 > lrB) sacc[nf][3] = -INFINITY;
            }
        }

        // ---- online softmax ----
        float mx0 = -INFINITY, mx1 = -INFINITY;
#pragma unroll
        for (int nf = 0; nf < 8; nf++) {
            mx0 = fmaxf(mx0, fmaxf(sacc[nf][0], sacc[nf][1]));
            mx1 = fmaxf(mx1, fmaxf(sacc[nf][2], sacc[nf][3]));
        }
        mx0 = fmaxf(mx0, __shfl_xor_sync(0xffffffffu, mx0, 1));
        mx0 = fmaxf(mx0, __shfl_xor_sync(0xffffffffu, mx0, 2));
        mx1 = fmaxf(mx1, __shfl_xor_sync(0xffffffffu, mx1, 1));
        mx1 = fmaxf(mx1, __shfl_xor_sync(0xffffffffu, mx1, 2));
        float mn0 = fmaxf(m0, mx0), mn1 = fmaxf(m1, mx1);
        float corr0 = __expf(m0 - mn0), corr1 = __expf(m1 - mn1);
        m0 = mn0; m1 = mn1;
        float rs0 = 0.f, rs1 = 0.f;
#pragma unroll
        for (int nf = 0; nf < 8; nf++) {
            sacc[nf][0] = __expf(sacc[nf][0] - m0);
            sacc[nf][1] = __expf(sacc[nf][1] - m0);
            sacc[nf][2] = __expf(sacc[nf][2] - m1);
            sacc[nf][3] = __expf(sacc[nf][3] - m1);
            rs0 += sacc[nf][0] + sacc[nf][1];
            rs1 += sacc[nf][2] + sacc[nf][3];
        }
        rs0 += __shfl_xor_sync(0xffffffffu, rs0, 1);
        rs0 += __shfl_xor_sync(0xffffffffu, rs0, 2);
        rs1 += __shfl_xor_sync(0xffffffffu, rs1, 1);
        rs1 += __shfl_xor_sync(0xffffffffu, rs1, 2);
        l0 = l0 * corr0 + rs0;
        l1 = l1 * corr1 + rs1;
#pragma unroll
        for (int nf = 0; nf < 8; nf++) {
            oacc[nf][0] *= corr0; oacc[nf][1] *= corr0;
            oacc[nf][2] *= corr1; oacc[nf][3] *= corr1;
        }

        // ---- O += P V : P single fp16, V fp16 hi/lo (2-product) ----
#pragma unroll
        for (int kc = 0; kc < 4; kc++) {
            uint32_t apf[4];
            apf[0] = pack2h(sacc[2 * kc][0],     sacc[2 * kc][1]);
            apf[1] = pack2h(sacc[2 * kc][2],     sacc[2 * kc][3]);
            apf[2] = pack2h(sacc[2 * kc + 1][0], sacc[2 * kc + 1][1]);
            apf[3] = pack2h(sacc[2 * kc + 1][2], sacc[2 * kc + 1][3]);
            const uint32_t vrow = (uint32_t)(kc * 16 + (lane & 15));
#pragma unroll
            for (int nf = 0; nf < 8; nf++) {
                const uint32_t voff = (uint32_t)((vrow * FA_STR + nf * 8) * 2);
                uint32_t bvh[2], bvl[2];
                ldsm_x2t(bvh, uVh + voff);
                ldsm_x2t(bvl, uVl + voff);
                mma16816h(oacc[nf], apf, bvh);
                mma16816h(oacc[nf], apf, bvl);
            }
        }
    }

    // ---- epilogue: normalize, split to bf16 hi/lo, store ----
    float inv0 = 1.f / l0, inv1 = 1.f / l1;
    const size_t goA = (qrow0 + wr + r0) * D_MODEL + (size_t)h * HEAD_D;
    const size_t goB = goA + 8 * D_MODEL;
#pragma unroll
    for (int nf = 0; nf < 8; nf++) {
        int d = nf * 8 + c0;
        uint32_t h0, lo0, h1, lo1;
        split2(oacc[nf][0] * inv0, oacc[nf][1] * inv0, h0, lo0);
        split2(oacc[nf][2] * inv1, oacc[nf][3] * inv1, h1, lo1);
        *(uint32_t*)(Oh_g + goA + d) = h0;
        *(uint32_t*)(Ol_g + goA + d) = lo0;
        *(uint32_t*)(Oh_g + goB + d) = h1;
        *(uint32_t*)(Ol_g + goB + d) = lo1;
    }
}

// ---------------------------------------------------------------------------
// kernel_launch: split(1) -> gemm_qkv(1) -> flash(1) -> gemm_o(1)
// ---------------------------------------------------------------------------
extern "C" void kernel_launch(void* const* d_in, const int* in_sizes, int n_in,
                              void* d_out, int out_size)
{
    const float* queries = (const float*)d_in[0];
    const float* keys    = (const float*)d_in[1];
    const float* values  = (const float*)d_in[2];
    const float* Wq = (const float*)d_in[3];
    const float* bq = (const float*)d_in[4];
    const float* Wk = (const float*)d_in[5];
    const float* bk = (const float*)d_in[6];
    const float* Wv = (const float*)d_in[7];
    const float* bv = (const float*)d_in[8];
    const float* Wo = (const float*)d_in[9];
    const float* bo = (const float*)d_in[10];
    float* out = (float*)d_out;

    __nv_bfloat16 *xh, *xl, *wh, *wl, *ah, *al;
    __half *qf, *kh, *kl, *vh, *vl;
    cudaGetSymbolAddress((void**)&xh, g_xh);
    cudaGetSymbolAddress((void**)&xl, g_xl);
    cudaGetSymbolAddress((void**)&wh, g_wh);
    cudaGetSymbolAddress((void**)&wl, g_wl);
    cudaGetSymbolAddress((void**)&qf, g_qf);
    cudaGetSymbolAddress((void**)&kh, g_kh);
    cudaGetSymbolAddress((void**)&kl, g_kl);
    cudaGetSymbolAddress((void**)&vh, g_vh);
    cudaGetSymbolAddress((void**)&vl, g_vl);
    cudaGetSymbolAddress((void**)&ah, g_ah);
    cudaGetSymbolAddress((void**)&al, g_al);

    cudaFuncSetAttribute(flash_mma_kernel,
                         cudaFuncAttributeMaxDynamicSharedMemorySize, FA_SMEM);
    cudaFuncSetAttribute(gemm_qkv_kernel,
                         cudaFuncAttributeMaxDynamicSharedMemorySize, GSMEM);
    cudaFuncSetAttribute(gemm_o_kernel,
                         cudaFuncAttributeMaxDynamicSharedMemorySize, GSMEM);

    // 1) Fused split of all 7 tensors (4 float4 per thread)
    dim3 sGrd((unsigned)(XSZ / 4 / 1024), 7);
    split_all_kernel<<<sGrd, 256>>>(queries, keys, values, Wq, Wk, Wv, Wo,
                                    xh, xl, wh, wl);

    // 2) Batched Q/K/V projections (Q: fp16 pre-scaled; K/V: fp16 hi/lo)
    dim3 gGrd(D_MODEL / 128, MTOT / 128, 3);   // (8, 32, 3)
    gemm_qkv_kernel<<<gGrd, 256, GSMEM>>>(xh, xl, wh, wl, bq, bk, bv,
                                          qf, kh, kl, vh, vl);

    // 3) Attention (64-row Q tiles, heaviest CTAs first)
    dim3 aGrd(LSEQ / 64, N_HEADS, NB);         // (32, 16, 2)
    flash_mma_kernel<<<aGrd, 128, FA_SMEM>>>(qf, kh, kl, vh, vl, ah, al);

    // 4) Output projection: fp32 out
    dim3 oGrd(D_MODEL / 128, MTOT / 128);      // (8, 32)
    gemm_o_kernel<<<oGrd, 256, GSMEM>>>(ah, al, wh + 3 * WSZ, wl + 3 * WSZ, bo, out);
}

// round 16
// speedup vs baseline: 2.4966x; 1.2706x over previous
#include <cuda_runtime.h>
#include <cuda_bf16.h>
#include <cuda_fp16.h>
#include <cstdint>
#include <math.h>

// Problem constants (fixed shapes from reference)
#define D_MODEL 1024
#define N_HEADS 16
#define HEAD_D  64
#define NB      2
#define LSEQ    2048
#define MTOT    (NB * LSEQ)   // 4096 rows total

#define XSZ ((size_t)MTOT * D_MODEL)     // 4M elements
#define WSZ ((size_t)D_MODEL * D_MODEL)  // 1M elements

// ---------------------------------------------------------------------------
// Scratch (allocation-free rule: __device__ globals)
// ---------------------------------------------------------------------------
__device__ __half g_xf[3][XSZ];   // q/k/v inputs, single fp16
__device__ __half g_wh[4][WSZ];   // Wq/Wk/Wv/Wo hi (fp16)
__device__ __half g_wl[4][WSZ];   // lo (fp16, subnormal-range ok)
__device__ __half g_qf[XSZ];      // projected Q, single fp16, pre-scaled by 1/8
__device__ __half g_kh[XSZ];      // projected K hi/lo (fp16)
__device__ __half g_kl[XSZ];
__device__ __half g_vh[XSZ];      // projected V hi/lo (fp16)
__device__ __half g_vl[XSZ];
__device__ __half g_af[XSZ];      // attn out, single fp16

// ---------------------------------------------------------------------------
// Small helpers
// ---------------------------------------------------------------------------
__device__ __forceinline__ uint32_t smem_u32(const void* p) {
    uint32_t a;
    asm("{ .reg .u64 t; cvta.to.shared.u64 t, %1; cvt.u32.u64 %0, t; }"
        : "=r"(a) : "l"(p));
    return a;
}
__device__ __forceinline__ void split2h(float x, float y, uint32_t& hi, uint32_t& lo) {
    __half hx = __float2half_rn(x), hy = __float2half_rn(y);
    __half2 hp; hp.x = hx; hp.y = hy;
    hi = *reinterpret_cast<uint32_t*>(&hp);
    __half2 lp = __floats2half2_rn(x - __half2float(hx), y - __half2float(hy));
    lo = *reinterpret_cast<uint32_t*>(&lp);
}
__device__ __forceinline__ uint32_t pack2h(float x, float y) {
    __half2 p = __floats2half2_rn(x, y);
    return *reinterpret_cast<uint32_t*>(&p);
}
__device__ __forceinline__ void mma16816h(float* c, const uint32_t* a, const uint32_t* b) {
    asm volatile(
        "mma.sync.aligned.m16n8k16.row.col.f32.f16.f16.f32 "
        "{%0,%1,%2,%3}, {%4,%5,%6,%7}, {%8,%9}, {%0,%1,%2,%3};"
        : "+f"(c[0]), "+f"(c[1]), "+f"(c[2]), "+f"(c[3])
        : "r"(a[0]), "r"(a[1]), "r"(a[2]), "r"(a[3]), "r"(b[0]), "r"(b[1]));
}
__device__ __forceinline__ void ldsm_x4(uint32_t* r, uint32_t a) {
    asm volatile("ldmatrix.sync.aligned.m8n8.x4.shared.b16 {%0,%1,%2,%3},[%4];"
                 : "=r"(r[0]), "=r"(r[1]), "=r"(r[2]), "=r"(r[3]) : "r"(a));
}
__device__ __forceinline__ void ldsm_x2(uint32_t* r, uint32_t a) {
    asm volatile("ldmatrix.sync.aligned.m8n8.x2.shared.b16 {%0,%1},[%2];"
                 : "=r"(r[0]), "=r"(r[1]) : "r"(a));
}
__device__ __forceinline__ void ldsm_x2t(uint32_t* r, uint32_t a) {
    asm volatile("ldmatrix.sync.aligned.m8n8.x2.trans.shared.b16 {%0,%1},[%2];"
                 : "=r"(r[0]), "=r"(r[1]) : "r"(a));
}
#define CP16(dst, src) \
    asm volatile("cp.async.cg.shared.global [%0], [%1], 16;" \
                 :: "r"(dst), "l"(src) : "memory")
#define CP_COMMIT() asm volatile("cp.async.commit_group;" ::: "memory")
#define CP_WAIT(n)  asm volatile("cp.async.wait_group %0;" :: "n"(n) : "memory")

// ---------------------------------------------------------------------------
// Fused split. Inputs (t 0-2): fp32 -> single fp16. Weights (t 3-6):
// fp32 -> fp16 hi/lo. 4 float4 per thread (MLP=4).
// ---------------------------------------------------------------------------
__global__ __launch_bounds__(256)
void split_all_kernel(const float* __restrict__ sx0, const float* __restrict__ sx1,
                      const float* __restrict__ sx2,
                      const float* __restrict__ sw0, const float* __restrict__ sw1,
                      const float* __restrict__ sw2, const float* __restrict__ sw3,
                      __half* __restrict__ xf,
                      __half* __restrict__ wh, __half* __restrict__ wl)
{
    const int t = blockIdx.y;
    const int base = blockIdx.x * 1024 + threadIdx.x;
    if (t < 3) {
        const float* src = (t == 0) ? sx0 : (t == 1) ? sx1 : sx2;
        __half* dst = xf + (size_t)t * XSZ;
        const int n4 = (int)(XSZ / 4);
        float4 v[4]; bool ok[4];
#pragma unroll
        for (int k = 0; k < 4; k++) {
            int i = base + k * 256;
            ok[k] = (i < n4);
            if (ok[k]) v[k] = ((const float4*)src)[i];
        }
#pragma unroll
        for (int k = 0; k < 4; k++) {
            if (!ok[k]) continue;
            int i = base + k * 256;
            ((uint2*)dst)[i] = make_uint2(pack2h(v[k].x, v[k].y), pack2h(v[k].z, v[k].w));
        }
    } else {
        int w = t - 3;
        const float* src = (w == 0) ? sw0 : (w == 1) ? sw1 : (w == 2) ? sw2 : sw3;
        __half* hi = wh + (size_t)w * WSZ;
        __half* lo = wl + (size_t)w * WSZ;
        const int n4 = (int)(WSZ / 4);
        float4 v[4]; bool ok[4];
#pragma unroll
        for (int k = 0; k < 4; k++) {
            int i = base + k * 256;
            ok[k] = (i < n4);
            if (ok[k]) v[k] = ((const float4*)src)[i];
        }
#pragma unroll
        for (int k = 0; k < 4; k++) {
            if (!ok[k]) continue;
            int i = base + k * 256;
            uint32_t h0, l0, h1, l1;
            split2h(v[k].x, v[k].y, h0, l0);
            split2h(v[k].z, v[k].w, h1, l1);
            ((uint2*)hi)[i] = make_uint2(h0, h1);
            ((uint2*)lo)[i] = make_uint2(l0, l1);
        }
    }
}

// ---------------------------------------------------------------------------
// GEMM core, asymmetric fp16: C = Xf * (Wh + Wl)^T, 2 fp16 MMAs per fragment.
// Skeleton kept line-for-line from the proven round-7 schedule:
// load next chunk -> CP_WAIT(1) -> sync -> compute -> sync. 3 smem arrays.
// ---------------------------------------------------------------------------
#define ASTR 40                     // smem row stride (fp16), conflict-free
#define GARR (128 * ASTR)           // elements per array (10240 B)
#define GSTAGE (3 * GARR)           // Af, Bh, Bl per stage
#define GSMEM (2 * GSTAGE * 2)      // 61440 B total (2 stages)

struct GemmCore {
    uint32_t uAf[2], uBh[2], uBl[2];
    uint32_t stoff, aoff, boff;
    int lrow, lhalf, warp_m, warp_n, r0, c0;
    float acc[4][4][4];

    __device__ __forceinline__ void init(__half* gsm, int tid) {
        const int lane = tid & 31;
        const int wid  = tid >> 5;
        warp_m = wid >> 2;
        warp_n = wid & 3;
        lrow  = tid >> 1;
        lhalf = (tid & 1) * 16;
        r0 = lane >> 2;
        c0 = (lane & 3) * 2;
        uint32_t uBase = smem_u32(gsm);
#pragma unroll
        for (int s = 0; s < 2; s++) {
            uint32_t sb = uBase + s * GSTAGE * 2;
            uAf[s] = sb;
            uBh[s] = sb + GARR * 2;
            uBl[s] = sb + 2 * GARR * 2;
        }
        stoff = (uint32_t)(lrow * ASTR + lhalf) * 2;
        const int ja = lane >> 3, ra = lane & 7;
        aoff = (uint32_t)(((warp_m * 64 + (ja & 1) * 8 + ra) * ASTR + (ja >> 1) * 8) * 2);
        boff = (uint32_t)(((warp_n * 32 + (ja >> 1) * 8 + ra) * ASTR + (ja & 1) * 8) * 2);
#pragma unroll
        for (int mf = 0; mf < 4; mf++)
#pragma unroll
            for (int nf = 0; nf < 4; nf++)
#pragma unroll
                for (int r = 0; r < 4; r++) acc[mf][nf][r] = 0.f;
    }

    __device__ __forceinline__ void load_chunk(
        const __half* Xf, const __half* Wh, const __half* Wl,
        int bm, int bn, int ch, int s)
    {
        const int kofs = ch * 32;
        const size_t xoff = (size_t)(bm + lrow) * D_MODEL + kofs + lhalf;
        const size_t woff = (size_t)(bn + lrow) * D_MODEL + kofs + lhalf;
        CP16(uAf[s] + stoff,      Xf + xoff);
        CP16(uAf[s] + stoff + 16, Xf + xoff + 8);
        CP16(uBh[s] + stoff,      Wh + woff);
        CP16(uBh[s] + stoff + 16, Wh + woff + 8);
        CP16(uBl[s] + stoff,      Wl + woff);
        CP16(uBl[s] + stoff + 16, Wl + woff + 8);
        CP_COMMIT();
    }

    __device__ __forceinline__ void compute_chunk(int s) {
#pragma unroll
        for (int kk = 0; kk < 32; kk += 16) {
            // B fragments: 2 x4 loads per (h,l) cover nf 0..3
            uint32_t bh[4][2], bl[4][2], t[4];
            ldsm_x4(t, uBh[s] + boff + kk * 2);
            bh[0][0] = t[0]; bh[0][1] = t[1]; bh[1][0] = t[2]; bh[1][1] = t[3];
            ldsm_x4(t, uBh[s] + boff + (16 * ASTR + kk) * 2);
            bh[2][0] = t[0]; bh[2][1] = t[1]; bh[3][0] = t[2]; bh[3][1] = t[3];
            ldsm_x4(t, uBl[s] + boff + kk * 2);
            bl[0][0] = t[0]; bl[0][1] = t[1]; bl[1][0] = t[2]; bl[1][1] = t[3];
            ldsm_x4(t, uBl[s] + boff + (16 * ASTR + kk) * 2);
            bl[2][0] = t[0]; bl[2][1] = t[1]; bl[3][0] = t[2]; bl[3][1] = t[3];

#pragma unroll
            for (int mf = 0; mf < 4; mf++) {
                uint32_t af[4];
                ldsm_x4(af, uAf[s] + aoff + (mf * 16 * ASTR + kk) * 2);
#pragma unroll
                for (int nf = 0; nf < 4; nf++) {
                    mma16816h(acc[mf][nf], af, bh[nf]);
                    mma16816h(acc[mf][nf], af, bl[nf]);
                }
            }
        }
    }

    __device__ __forceinline__ void run(
        const __half* Xf, const __half* Wh, const __half* Wl, int bm, int bn)
    {
        load_chunk(Xf, Wh, Wl, bm, bn, 0, 0);
        const int NCH = D_MODEL / 32;   // 32
        for (int ch = 0; ch < NCH; ch++) {
            const int s = ch & 1;
            if (ch + 1 < NCH) {
                load_chunk(Xf, Wh, Wl, bm, bn, ch + 1, s ^ 1);
                CP_WAIT(1);
            } else {
                CP_WAIT(0);
            }
            __syncthreads();
            compute_chunk(s);
            __syncthreads();
        }
    }
};

// Batched QKV projection: blockIdx.z selects (input, weight, bias, output).
// t==0 (Q): single fp16, pre-scaled by 1/8.  t==1 (K), t==2 (V): fp16 hi/lo.
__global__ __launch_bounds__(256, 2)
void gemm_qkv_kernel(const __half* __restrict__ xf,
                     const __half* __restrict__ wh, const __half* __restrict__ wl,
                     const float* __restrict__ bq, const float* __restrict__ bk,
                     const float* __restrict__ bv,
                     __half* __restrict__ qf,
                     __half* __restrict__ kh, __half* __restrict__ kl,
                     __half* __restrict__ vh, __half* __restrict__ vl)
{
    extern __shared__ __half gsm[];
    const int t  = blockIdx.z;
    const int bm = blockIdx.y * 128;
    const int bn = blockIdx.x * 128;

    const __half* Xf = xf + (size_t)t * XSZ;
    const __half* Wh = wh + (size_t)t * WSZ;
    const __half* Wl = wl + (size_t)t * WSZ;
    const float* bias = (t == 0) ? bq : (t == 1) ? bk : bv;
    uint16_t* Ch = (t == 0) ? (uint16_t*)qf : (t == 1) ? (uint16_t*)kh : (uint16_t*)vh;
    uint16_t* Cl = (t == 1) ? (uint16_t*)kl : (uint16_t*)vl;   // unused for t==0

    GemmCore g;
    g.init(gsm, threadIdx.x);
    g.run(Xf, Wh, Wl, bm, bn);

#pragma unroll
    for (int mf = 0; mf < 4; mf++) {
        int row = bm + g.warp_m * 64 + mf * 16 + g.r0;
#pragma unroll
        for (int nf = 0; nf < 4; nf++) {
            int col = bn + g.warp_n * 32 + nf * 8 + g.c0;
            float2 bv2 = *(const float2*)(bias + col);
            float s00 = g.acc[mf][nf][0] + bv2.x;
            float s01 = g.acc[mf][nf][1] + bv2.y;
            float s10 = g.acc[mf][nf][2] + bv2.x;
            float s11 = g.acc[mf][nf][3] + bv2.y;
            if (t == 0) {
                *(uint32_t*)(Ch + (size_t)row * D_MODEL + col) =
                    pack2h(s00 * 0.125f, s01 * 0.125f);
                *(uint32_t*)(Ch + (size_t)(row + 8) * D_MODEL + col) =
                    pack2h(s10 * 0.125f, s11 * 0.125f);
            } else {
                uint32_t h0, l0, h1, l1;
                split2h(s00, s01, h0, l0);
                split2h(s10, s11, h1, l1);
                *(uint32_t*)(Ch + (size_t)row * D_MODEL + col)       = h0;
                *(uint32_t*)(Cl + (size_t)row * D_MODEL + col)       = l0;
                *(uint32_t*)(Ch + (size_t)(row + 8) * D_MODEL + col) = h1;
                *(uint32_t*)(Cl + (size_t)(row + 8) * D_MODEL + col) = l1;
            }
        }
    }
}

// Output projection: fp32 out.
__global__ __launch_bounds__(256, 2)
void gemm_o_kernel(const __half* __restrict__ Xf,
                   const __half* __restrict__ Wh, const __half* __restrict__ Wl,
                   const float* __restrict__ bias, float* __restrict__ Cf)
{
    extern __shared__ __half gsm[];
    const int bm = blockIdx.y * 128;
    const int bn = blockIdx.x * 128;

    GemmCore g;
    g.init(gsm, threadIdx.x);
    g.run(Xf, Wh, Wl, bm, bn);

#pragma unroll
    for (int mf = 0; mf < 4; mf++) {
        int row = bm + g.warp_m * 64 + mf * 16 + g.r0;
#pragma unroll
        for (int nf = 0; nf < 4; nf++) {
            int col = bn + g.warp_n * 32 + nf * 8 + g.c0;
            float2 bv2 = *(const float2*)(bias + col);
            *(float2*)(Cf + (size_t)row * D_MODEL + col) =
                make_float2(g.acc[mf][nf][0] + bv2.x, g.acc[mf][nf][1] + bv2.y);
            *(float2*)(Cf + (size_t)(row + 8) * D_MODEL + col) =
                make_float2(g.acc[mf][nf][2] + bv2.x, g.acc[mf][nf][3] + bv2.y);
        }
    }
}

// ---------------------------------------------------------------------------
// Flash attention (causal). QK: Qf(fp16, pre-scaled) x K fp16 hi/lo -> 2 MMAs.
// PV: P single fp16 x V fp16 hi/lo -> 2 MMAs. Output single fp16.
// Descending qt order.
// ---------------------------------------------------------------------------
#define FA_STR 72                   // [64][72] 16-bit tiles, conflict-free ldmatrix
#define FA_TILE (64 * FA_STR)       // elements per array
#define FT2 (FA_TILE * 2)           // bytes per array (9216)
#define FA_SMEM (9 * FT2)           // Q(1) + 2 stages x KV(4) = 82944 B

__global__ __launch_bounds__(128, 2)
void flash_mma_kernel(const __half* __restrict__ Qf_g,
                      const __half* __restrict__ Kh_g, const __half* __restrict__ Kl_g,
                      const __half* __restrict__ Vh_g, const __half* __restrict__ Vl_g,
                      __half* __restrict__ Of_g)
{
    extern __shared__ __half fsmh[];
    __half* sQf = fsmh;

    const int tid  = threadIdx.x;
    const int lane = tid & 31;
    const int wid  = tid >> 5;
    const int qt   = (int)(gridDim.x - 1 - blockIdx.x);   // descending work order
    const int h    = blockIdx.y;
    const int n    = blockIdx.z;

    const uint32_t uQf = smem_u32(sQf);
    const uint32_t uKV0 = uQf + FT2;   // stage 0 base

    const int wr = wid * 16;      // warp's Q-row base within tile
    const int r0 = lane >> 2;     // 0..7
    const int c0 = (lane & 3) * 2;

    // Load Q tile (single fp16), natural [row][d] layout.
    const size_t qrow0 = (size_t)(n * LSEQ + qt * 64);
    const size_t gq = qrow0 * D_MODEL + (size_t)h * HEAD_D;
#pragma unroll
    for (int i = 0; i < 4; i++) {
        int f = tid + i * 128;          // 0..511
        int row = f >> 3, c8 = (f & 7) * 8;
        *(uint4*)(sQf + row * FA_STR + c8) =
            *(const uint4*)(Qf_g + gq + (size_t)row * D_MODEL + c8);
    }

    // K/V chunk loader via cp.async (16x16B per thread)
    auto load_kv = [&](int kt, int s) {
        const uint32_t base = uKV0 + (uint32_t)s * 4 * FT2;
        const size_t gk = ((size_t)(n * LSEQ + kt * 64)) * D_MODEL + (size_t)h * HEAD_D;
#pragma unroll
        for (int i = 0; i < 4; i++) {
            int f = tid + i * 128;
            int row = f >> 3, c8 = (f & 7) * 8;
            uint32_t so = (uint32_t)(row * FA_STR + c8) * 2;
            size_t go = gk + (size_t)row * D_MODEL + c8;
            CP16(base + so,           Kh_g + go);
            CP16(base + FT2 + so,     Kl_g + go);
            CP16(base + 2 * FT2 + so, Vh_g + go);
            CP16(base + 3 * FT2 + so, Vl_g + go);
        }
        CP_COMMIT();
    };

    float oacc[8][4];
#pragma unroll
    for (int nf = 0; nf < 8; nf++)
#pragma unroll
        for (int j = 0; j < 4; j++) oacc[nf][j] = 0.f;
    float m0 = -INFINITY, m1 = -INFINITY, l0 = 0.f, l1 = 0.f;

    load_kv(0, 0);

    for (int kt = 0; kt <= qt; kt++) {
        const int s = kt & 1;
        const uint32_t uKh = uKV0 + (uint32_t)s * 4 * FT2;
        const uint32_t uKl = uKh + FT2;
        const uint32_t uVh = uKh + 2 * FT2;
        const uint32_t uVl = uKh + 3 * FT2;

        CP_WAIT(0);        // current stage's copies arrived
        __syncthreads();   // all warps done with stage s^1 + copies visible
        if (kt < qt) load_kv(kt + 1, s ^ 1);   // prefetch overlaps compute below

        // ---- S = Qf K^T (fp16, 2-product) ----
        float sacc[8][4];
#pragma unroll
        for (int nf = 0; nf < 8; nf++)
#pragma unroll
            for (int j = 0; j < 4; j++) sacc[nf][j] = 0.f;

#pragma unroll
        for (int kc = 0; kc < 4; kc++) {
            const uint32_t aoff = (uint32_t)(((wr + (lane & 15)) * FA_STR
                                  + kc * 16 + (lane >> 4) * 8) * 2);
            uint32_t aqf[4];
            ldsm_x4(aqf, uQf + aoff);
            const uint32_t brow = (lane & 7);
            const uint32_t bk8  = ((lane >> 3) & 1) * 8;
#pragma unroll
            for (int nf = 0; nf < 8; nf++) {
                const uint32_t boff = (uint32_t)(((nf * 8 + brow) * FA_STR
                                      + kc * 16 + bk8) * 2);
                uint32_t bkh[2], bkl[2];
                ldsm_x2(bkh, uKh + boff);
                ldsm_x2(bkl, uKl + boff);
                mma16816h(sacc[nf], aqf, bkh);
                mma16816h(sacc[nf], aqf, bkl);
            }
        }

        // ---- causal mask (scale already folded into Q) ----
        if (kt == qt) {
#pragma unroll
            for (int nf = 0; nf < 8; nf++) {
                int col = nf * 8 + c0;
                int lrA = wr + r0, lrB = wr + r0 + 8;
                if (col     > lrA) sacc[nf][0] = -INFINITY;
                if (col + 1 > lrA) sacc[nf][1] = -INFINITY;
                if (col     > lrB) sacc[nf][2] = -INFINITY;
                if (col + 1 > lrB) sacc[nf][3] = -INFINITY;
            }
        }

        // ---- online softmax ----
        float mx0 = -INFINITY, mx1 = -INFINITY;
#pragma unroll
        for (int nf = 0; nf < 8; nf++) {
            mx0 = fmaxf(mx0, fmaxf(sacc[nf][0], sacc[nf][1]));
            mx1 = fmaxf(mx1, fmaxf(sacc[nf][2], sacc[nf][3]));
        }
        mx0 = fmaxf(mx0, __shfl_xor_sync(0xffffffffu, mx0, 1));
        mx0 = fmaxf(mx0, __shfl_xor_sync(0xffffffffu, mx0, 2));
        mx1 = fmaxf(mx1, __shfl_xor_sync(0xffffffffu, mx1, 1));
        mx1 = fmaxf(mx1, __shfl_xor_sync(0xffffffffu, mx1, 2));
        float mn0 = fmaxf(m0, mx0), mn1 = fmaxf(m1, mx1);
        float corr0 = __expf(m0 - mn0), corr1 = __expf(m1 - mn1);
        m0 = mn0; m1 = mn1;
        float rs0 = 0.f, rs1 = 0.f;
#pragma unroll
        for (int nf = 0; nf < 8; nf++) {
            sacc[nf][0] = __expf(sacc[nf][0] - m0);
            sacc[nf][1] = __expf(sacc[nf][1] - m0);
            sacc[nf][2] = __expf(sacc[nf][2] - m1);
            sacc[nf][3] = __expf(sacc[nf][3] - m1);
            rs0 += sacc[nf][0] + sacc[nf][1];
            rs1 += sacc[nf][2] + sacc[nf][3];
        }
        rs0 += __shfl_xor_sync(0xffffffffu, rs0, 1);
        rs0 += __shfl_xor_sync(0xffffffffu, rs0, 2);
        rs1 += __shfl_xor_sync(0xffffffffu, rs1, 1);
        rs1 += __shfl_xor_sync(0xffffffffu, rs1, 2);
        l0 = l0 * corr0 + rs0;
        l1 = l1 * corr1 + rs1;
#pragma unroll
        for (int nf = 0; nf < 8; nf++) {
            oacc[nf][0] *= corr0; oacc[nf][1] *= corr0;
            oacc[nf][2] *= corr1; oacc[nf][3] *= corr1;
        }

        // ---- O += P V : P single fp16, V fp16 hi/lo (2-product) ----
#pragma unroll
        for (int kc = 0; kc < 4; kc++) {
            uint32_t apf[4];
            apf[0] = pack2h(sacc[2 * kc][0],     sacc[2 * kc][1]);
            apf[1] = pack2h(sacc[2 * kc][2],     sacc[2 * kc][3]);
            apf[2] = pack2h(sacc[2 * kc + 1][0], sacc[2 * kc + 1][1]);
            apf[3] = pack2h(sacc[2 * kc + 1][2], sacc[2 * kc + 1][3]);
            const uint32_t vrow = (uint32_t)(kc * 16 + (lane & 15));
#pragma unroll
            for (int nf = 0; nf < 8; nf++) {
                const uint32_t voff = (uint32_t)((vrow * FA_STR + nf * 8) * 2);
                uint32_t bvh[2], bvl[2];
                ldsm_x2t(bvh, uVh + voff);
                ldsm_x2t(bvl, uVl + voff);
                mma16816h(oacc[nf], apf, bvh);
                mma16816h(oacc[nf], apf, bvl);
            }
        }
    }

    // ---- epilogue: normalize, store single fp16 ----
    float inv0 = 1.f / l0, inv1 = 1.f / l1;
    const size_t goA = (qrow0 + wr + r0) * D_MODEL + (size_t)h * HEAD_D;
    const size_t goB = goA + 8 * D_MODEL;
#pragma unroll
    for (int nf = 0; nf < 8; nf++) {
        int d = nf * 8 + c0;
        *(uint32_t*)(Of_g + goA + d) = pack2h(oacc[nf][0] * inv0, oacc[nf][1] * inv0);
        *(uint32_t*)(Of_g + goB + d) = pack2h(oacc[nf][2] * inv1, oacc[nf][3] * inv1);
    }
}

// ---------------------------------------------------------------------------
// kernel_launch: split(1) -> gemm_qkv(1) -> flash(1) -> gemm_o(1)
// ---------------------------------------------------------------------------
extern "C" void kernel_launch(void* const* d_in, const int* in_sizes, int n_in,
                              void* d_out, int out_size)
{
    const float* queries = (const float*)d_in[0];
    const float* keys    = (const float*)d_in[1];
    const float* values  = (const float*)d_in[2];
    const float* Wq = (const float*)d_in[3];
    const float* bq = (const float*)d_in[4];
    const float* Wk = (const float*)d_in[5];
    const float* bk = (const float*)d_in[6];
    const float* Wv = (const float*)d_in[7];
    const float* bv = (const float*)d_in[8];
    const float* Wo = (const float*)d_in[9];
    const float* bo = (const float*)d_in[10];
    float* out = (float*)d_out;

    __half *xf, *wh, *wl, *qf, *kh, *kl, *vh, *vl, *af;
    cudaGetSymbolAddress((void**)&xf, g_xf);
    cudaGetSymbolAddress((void**)&wh, g_wh);
    cudaGetSymbolAddress((void**)&wl, g_wl);
    cudaGetSymbolAddress((void**)&qf, g_qf);
    cudaGetSymbolAddress((void**)&kh, g_kh);
    cudaGetSymbolAddress((void**)&kl, g_kl);
    cudaGetSymbolAddress((void**)&vh, g_vh);
    cudaGetSymbolAddress((void**)&vl, g_vl);
    cudaGetSymbolAddress((void**)&af, g_af);

    cudaFuncSetAttribute(flash_mma_kernel,
                         cudaFuncAttributeMaxDynamicSharedMemorySize, FA_SMEM);
    cudaFuncSetAttribute(gemm_qkv_kernel,
                         cudaFuncAttributeMaxDynamicSharedMemorySize, GSMEM);
    cudaFuncSetAttribute(gemm_o_kernel,
                         cudaFuncAttributeMaxDynamicSharedMemorySize, GSMEM);

    // 1) Fused split of all 7 tensors
    dim3 sGrd((unsigned)(XSZ / 4 / 1024), 7);
    split_all_kernel<<<sGrd, 256>>>(queries, keys, values, Wq, Wk, Wv, Wo,
                                    xf, wh, wl);

    // 2) Batched Q/K/V projections (Q: fp16 pre-scaled; K/V: fp16 hi/lo)
    dim3 gGrd(D_MODEL / 128, MTOT / 128, 3);   // (8, 32, 3)
    gemm_qkv_kernel<<<gGrd, 256, GSMEM>>>(xf, wh, wl, bq, bk, bv,
                                          qf, kh, kl, vh, vl);

    // 3) Attention (64-row Q tiles, heaviest CTAs first)
    dim3 aGrd(LSEQ / 64, N_HEADS, NB);         // (32, 16, 2)
    flash_mma_kernel<<<aGrd, 128, FA_SMEM>>>(qf, kh, kl, vh, vl, af);

    // 4) Output projection: fp32 out
    dim3 oGrd(D_MODEL / 128, MTOT / 128);      // (8, 32)
    gemm_o_kernel<<<oGrd, 256, GSMEM>>>(af, wh + 3 * WSZ, wl + 3 * WSZ, bo, out);
}

// round 17
// speedup vs baseline: 3.1939x; 1.2793x over previous
#include <cuda_runtime.h>
#include <cuda_bf16.h>
#include <cuda_fp16.h>
#include <cstdint>
#include <math.h>

// Problem constants (fixed shapes from reference)
#define D_MODEL 1024
#define N_HEADS 16
#define HEAD_D  64
#define NB      2
#define LSEQ    2048
#define MTOT    (NB * LSEQ)   // 4096 rows total

#define XSZ ((size_t)MTOT * D_MODEL)     // 4M elements
#define WSZ ((size_t)D_MODEL * D_MODEL)  // 1M elements

// ---------------------------------------------------------------------------
// Scratch (allocation-free rule: __device__ globals)
// ---------------------------------------------------------------------------
__device__ __half g_xf[3][XSZ];   // q/k/v inputs, single fp16
__device__ __half g_wf[4][WSZ];   // Wq/Wk/Wv/Wo, single fp16
__device__ __half g_qf[XSZ];      // projected Q, single fp16, pre-scaled by 1/8
__device__ __half g_kh[XSZ];      // projected K hi/lo (fp16)
__device__ __half g_kl[XSZ];
__device__ __half g_vh[XSZ];      // projected V hi/lo (fp16)
__device__ __half g_vl[XSZ];
__device__ __half g_af[XSZ];      // attn out, single fp16

// ---------------------------------------------------------------------------
// Small helpers
// ---------------------------------------------------------------------------
__device__ __forceinline__ uint32_t smem_u32(const void* p) {
    uint32_t a;
    asm("{ .reg .u64 t; cvta.to.shared.u64 t, %1; cvt.u32.u64 %0, t; }"
        : "=r"(a) : "l"(p));
    return a;
}
__device__ __forceinline__ void split2h(float x, float y, uint32_t& hi, uint32_t& lo) {
    __half hx = __float2half_rn(x), hy = __float2half_rn(y);
    __half2 hp; hp.x = hx; hp.y = hy;
    hi = *reinterpret_cast<uint32_t*>(&hp);
    __half2 lp = __floats2half2_rn(x - __half2float(hx), y - __half2float(hy));
    lo = *reinterpret_cast<uint32_t*>(&lp);
}
__device__ __forceinline__ uint32_t pack2h(float x, float y) {
    __half2 p = __floats2half2_rn(x, y);
    return *reinterpret_cast<uint32_t*>(&p);
}
__device__ __forceinline__ void mma16816h(float* c, const uint32_t* a, const uint32_t* b) {
    asm volatile(
        "mma.sync.aligned.m16n8k16.row.col.f32.f16.f16.f32 "
        "{%0,%1,%2,%3}, {%4,%5,%6,%7}, {%8,%9}, {%0,%1,%2,%3};"
        : "+f"(c[0]), "+f"(c[1]), "+f"(c[2]), "+f"(c[3])
        : "r"(a[0]), "r"(a[1]), "r"(a[2]), "r"(a[3]), "r"(b[0]), "r"(b[1]));
}
__device__ __forceinline__ void ldsm_x4(uint32_t* r, uint32_t a) {
    asm volatile("ldmatrix.sync.aligned.m8n8.x4.shared.b16 {%0,%1,%2,%3},[%4];"
                 : "=r"(r[0]), "=r"(r[1]), "=r"(r[2]), "=r"(r[3]) : "r"(a));
}
__device__ __forceinline__ void ldsm_x2(uint32_t* r, uint32_t a) {
    asm volatile("ldmatrix.sync.aligned.m8n8.x2.shared.b16 {%0,%1},[%2];"
                 : "=r"(r[0]), "=r"(r[1]) : "r"(a));
}
__device__ __forceinline__ void ldsm_x2t(uint32_t* r, uint32_t a) {
    asm volatile("ldmatrix.sync.aligned.m8n8.x2.trans.shared.b16 {%0,%1},[%2];"
                 : "=r"(r[0]), "=r"(r[1]) : "r"(a));
}
#define CP16(dst, src) \
    asm volatile("cp.async.cg.shared.global [%0], [%1], 16;" \
                 :: "r"(dst), "l"(src) : "memory")
#define CP_COMMIT() asm volatile("cp.async.commit_group;" ::: "memory")
#define CP_WAIT(n)  asm volatile("cp.async.wait_group %0;" :: "n"(n) : "memory")

// ---------------------------------------------------------------------------
// Fused split: all 7 tensors fp32 -> single fp16. 4 float4 per thread.
// blockIdx.y = tensor (0-2 inputs at XSZ, 3-6 weights at WSZ).
// ---------------------------------------------------------------------------
__global__ __launch_bounds__(256)
void split_all_kernel(const float* __restrict__ sx0, const float* __restrict__ sx1,
                      const float* __restrict__ sx2,
                      const float* __restrict__ sw0, const float* __restrict__ sw1,
                      const float* __restrict__ sw2, const float* __restrict__ sw3,
                      __half* __restrict__ xf, __half* __restrict__ wf)
{
    const int t = blockIdx.y;
    const float* src;
    __half* dst;
    int n4;
    if (t < 3) {
        src = (t == 0) ? sx0 : (t == 1) ? sx1 : sx2;
        dst = xf + (size_t)t * XSZ;
        n4 = (int)(XSZ / 4);
    } else {
        int w = t - 3;
        src = (w == 0) ? sw0 : (w == 1) ? sw1 : (w == 2) ? sw2 : sw3;
        dst = wf + (size_t)w * WSZ;
        n4 = (int)(WSZ / 4);
    }
    const int base = blockIdx.x * 1024 + threadIdx.x;
    float4 v[4]; bool ok[4];
#pragma unroll
    for (int k = 0; k < 4; k++) {
        int i = base + k * 256;
        ok[k] = (i < n4);
        if (ok[k]) v[k] = ((const float4*)src)[i];
    }
#pragma unroll
    for (int k = 0; k < 4; k++) {
        if (!ok[k]) continue;
        int i = base + k * 256;
        ((uint2*)dst)[i] = make_uint2(pack2h(v[k].x, v[k].y), pack2h(v[k].z, v[k].w));
    }
}

// ---------------------------------------------------------------------------
// GEMM core, pure fp16: C = Xf * Wf^T, 1 fp16 MMA per fragment.
// Skeleton kept line-for-line from the proven round-7 schedule:
// load next chunk -> CP_WAIT(1) -> sync -> compute -> sync. 2 smem arrays.
// ---------------------------------------------------------------------------
#define ASTR 40                     // smem row stride (fp16), conflict-free
#define GARR (128 * ASTR)           // elements per array (10240 B)
#define GSTAGE (2 * GARR)           // Af, Bf per stage
#define GSMEM (2 * GSTAGE * 2)      // 40960 B total (2 stages)

struct GemmCore {
    uint32_t uAf[2], uBf[2];
    uint32_t stoff, aoff, boff;
    int lrow, lhalf, warp_m, warp_n, r0, c0;
    float acc[4][4][4];

    __device__ __forceinline__ void init(__half* gsm, int tid) {
        const int lane = tid & 31;
        const int wid  = tid >> 5;
        warp_m = wid >> 2;
        warp_n = wid & 3;
        lrow  = tid >> 1;
        lhalf = (tid & 1) * 16;
        r0 = lane >> 2;
        c0 = (lane & 3) * 2;
        uint32_t uBase = smem_u32(gsm);
#pragma unroll
        for (int s = 0; s < 2; s++) {
            uint32_t sb = uBase + s * GSTAGE * 2;
            uAf[s] = sb;
            uBf[s] = sb + GARR * 2;
        }
        stoff = (uint32_t)(lrow * ASTR + lhalf) * 2;
        const int ja = lane >> 3, ra = lane & 7;
        aoff = (uint32_t)(((warp_m * 64 + (ja & 1) * 8 + ra) * ASTR + (ja >> 1) * 8) * 2);
        boff = (uint32_t)(((warp_n * 32 + (ja >> 1) * 8 + ra) * ASTR + (ja & 1) * 8) * 2);
#pragma unroll
        for (int mf = 0; mf < 4; mf++)
#pragma unroll
            for (int nf = 0; nf < 4; nf++)
#pragma unroll
                for (int r = 0; r < 4; r++) acc[mf][nf][r] = 0.f;
    }

    __device__ __forceinline__ void load_chunk(
        const __half* Xf, const __half* Wf, int bm, int bn, int ch, int s)
    {
        const int kofs = ch * 32;
        const size_t xoff = (size_t)(bm + lrow) * D_MODEL + kofs + lhalf;
        const size_t woff = (size_t)(bn + lrow) * D_MODEL + kofs + lhalf;
        CP16(uAf[s] + stoff,      Xf + xoff);
        CP16(uAf[s] + stoff + 16, Xf + xoff + 8);
        CP16(uBf[s] + stoff,      Wf + woff);
        CP16(uBf[s] + stoff + 16, Wf + woff + 8);
        CP_COMMIT();
    }

    __device__ __forceinline__ void compute_chunk(int s) {
#pragma unroll
        for (int kk = 0; kk < 32; kk += 16) {
            // B fragments: 2 x4 loads cover nf 0..3
            uint32_t bf[4][2], t[4];
            ldsm_x4(t, uBf[s] + boff + kk * 2);
            bf[0][0] = t[0]; bf[0][1] = t[1]; bf[1][0] = t[2]; bf[1][1] = t[3];
            ldsm_x4(t, uBf[s] + boff + (16 * ASTR + kk) * 2);
            bf[2][0] = t[0]; bf[2][1] = t[1]; bf[3][0] = t[2]; bf[3][1] = t[3];

#pragma unroll
            for (int mf = 0; mf < 4; mf++) {
                uint32_t af[4];
                ldsm_x4(af, uAf[s] + aoff + (mf * 16 * ASTR + kk) * 2);
#pragma unroll
                for (int nf = 0; nf < 4; nf++)
                    mma16816h(acc[mf][nf], af, bf[nf]);
            }
        }
    }

    __device__ __forceinline__ void run(
        const __half* Xf, const __half* Wf, int bm, int bn)
    {
        load_chunk(Xf, Wf, bm, bn, 0, 0);
        const int NCH = D_MODEL / 32;   // 32
        for (int ch = 0; ch < NCH; ch++) {
            const int s = ch & 1;
            if (ch + 1 < NCH) {
                load_chunk(Xf, Wf, bm, bn, ch + 1, s ^ 1);
                CP_WAIT(1);
            } else {
                CP_WAIT(0);
            }
            __syncthreads();
            compute_chunk(s);
            __syncthreads();
        }
    }
};

// Batched QKV projection: blockIdx.z selects (input, weight, bias, output).
// t==0 (Q): single fp16, pre-scaled by 1/8.  t==1 (K), t==2 (V): fp16 hi/lo.
__global__ __launch_bounds__(256, 2)
void gemm_qkv_kernel(const __half* __restrict__ xf, const __half* __restrict__ wf,
                     const float* __restrict__ bq, const float* __restrict__ bk,
                     const float* __restrict__ bv,
                     __half* __restrict__ qf,
                     __half* __restrict__ kh, __half* __restrict__ kl,
                     __half* __restrict__ vh, __half* __restrict__ vl)
{
    extern __shared__ __half gsm[];
    const int t  = blockIdx.z;
    const int bm = blockIdx.y * 128;
    const int bn = blockIdx.x * 128;

    const __half* Xf = xf + (size_t)t * XSZ;
    const __half* Wf = wf + (size_t)t * WSZ;
    const float* bias = (t == 0) ? bq : (t == 1) ? bk : bv;
    uint16_t* Ch = (t == 0) ? (uint16_t*)qf : (t == 1) ? (uint16_t*)kh : (uint16_t*)vh;
    uint16_t* Cl = (t == 1) ? (uint16_t*)kl : (uint16_t*)vl;   // unused for t==0

    GemmCore g;
    g.init(gsm, threadIdx.x);
    g.run(Xf, Wf, bm, bn);

#pragma unroll
    for (int mf = 0; mf < 4; mf++) {
        int row = bm + g.warp_m * 64 + mf * 16 + g.r0;
#pragma unroll
        for (int nf = 0; nf < 4; nf++) {
            int col = bn + g.warp_n * 32 + nf * 8 + g.c0;
            float2 bv2 = *(const float2*)(bias + col);
            float s00 = g.acc[mf][nf][0] + bv2.x;
            float s01 = g.acc[mf][nf][1] + bv2.y;
            float s10 = g.acc[mf][nf][2] + bv2.x;
            float s11 = g.acc[mf][nf][3] + bv2.y;
            if (t == 0) {
                *(uint32_t*)(Ch + (size_t)row * D_MODEL + col) =
                    pack2h(s00 * 0.125f, s01 * 0.125f);
                *(uint32_t*)(Ch + (size_t)(row + 8) * D_MODEL + col) =
                    pack2h(s10 * 0.125f, s11 * 0.125f);
            } else {
                uint32_t h0, l0, h1, l1;
                split2h(s00, s01, h0, l0);
                split2h(s10, s11, h1, l1);
                *(uint32_t*)(Ch + (size_t)row * D_MODEL + col)       = h0;
                *(uint32_t*)(Cl + (size_t)row * D_MODEL + col)       = l0;
                *(uint32_t*)(Ch + (size_t)(row + 8) * D_MODEL + col) = h1;
                *(uint32_t*)(Cl + (size_t)(row + 8) * D_MODEL + col) = l1;
            }
        }
    }
}

// Output projection: fp32 out.
__global__ __launch_bounds__(256, 2)
void gemm_o_kernel(const __half* __restrict__ Xf, const __half* __restrict__ Wf,
                   const float* __restrict__ bias, float* __restrict__ Cf)
{
    extern __shared__ __half gsm[];
    const int bm = blockIdx.y * 128;
    const int bn = blockIdx.x * 128;

    GemmCore g;
    g.init(gsm, threadIdx.x);
    g.run(Xf, Wf, bm, bn);

#pragma unroll
    for (int mf = 0; mf < 4; mf++) {
        int row = bm + g.warp_m * 64 + mf * 16 + g.r0;
#pragma unroll
        for (int nf = 0; nf < 4; nf++) {
            int col = bn + g.warp_n * 32 + nf * 8 + g.c0;
            float2 bv2 = *(const float2*)(bias + col);
            *(float2*)(Cf + (size_t)row * D_MODEL + col) =
                make_float2(g.acc[mf][nf][0] + bv2.x, g.acc[mf][nf][1] + bv2.y);
            *(float2*)(Cf + (size_t)(row + 8) * D_MODEL + col) =
                make_float2(g.acc[mf][nf][2] + bv2.x, g.acc[mf][nf][3] + bv2.y);
        }
    }
}

// ---------------------------------------------------------------------------
// Flash attention (causal). QK: Qf(fp16, pre-scaled) x K fp16 hi/lo -> 2 MMAs.
// PV: P single fp16 x V fp16 hi/lo -> 2 MMAs. Output single fp16.
// Descending qt order. (Unchanged from round 16.)
// ---------------------------------------------------------------------------
#define FA_STR 72                   // [64][72] 16-bit tiles, conflict-free ldmatrix
#define FA_TILE (64 * FA_STR)       // elements per array
#define FT2 (FA_TILE * 2)           // bytes per array (9216)
#define FA_SMEM (9 * FT2)           // Q(1) + 2 stages x KV(4) = 82944 B

__global__ __launch_bounds__(128, 2)
void flash_mma_kernel(const __half* __restrict__ Qf_g,
                      const __half* __restrict__ Kh_g, const __half* __restrict__ Kl_g,
                      const __half* __restrict__ Vh_g, const __half* __restrict__ Vl_g,
                      __half* __restrict__ Of_g)
{
    extern __shared__ __half fsmh[];
    __half* sQf = fsmh;

    const int tid  = threadIdx.x;
    const int lane = tid & 31;
    const int wid  = tid >> 5;
    const int qt   = (int)(gridDim.x - 1 - blockIdx.x);   // descending work order
    const int h    = blockIdx.y;
    const int n    = blockIdx.z;

    const uint32_t uQf = smem_u32(sQf);
    const uint32_t uKV0 = uQf + FT2;   // stage 0 base

    const int wr = wid * 16;      // warp's Q-row base within tile
    const int r0 = lane >> 2;     // 0..7
    const int c0 = (lane & 3) * 2;

    // Load Q tile (single fp16), natural [row][d] layout.
    const size_t qrow0 = (size_t)(n * LSEQ + qt * 64);
    const size_t gq = qrow0 * D_MODEL + (size_t)h * HEAD_D;
#pragma unroll
    for (int i = 0; i < 4; i++) {
        int f = tid + i * 128;          // 0..511
        int row = f >> 3, c8 = (f & 7) * 8;
        *(uint4*)(sQf + row * FA_STR + c8) =
            *(const uint4*)(Qf_g + gq + (size_t)row * D_MODEL + c8);
    }

    // K/V chunk loader via cp.async (16x16B per thread)
    auto load_kv = [&](int kt, int s) {
        const uint32_t base = uKV0 + (uint32_t)s * 4 * FT2;
        const size_t gk = ((size_t)(n * LSEQ + kt * 64)) * D_MODEL + (size_t)h * HEAD_D;
#pragma unroll
        for (int i = 0; i < 4; i++) {
            int f = tid + i * 128;
            int row = f >> 3, c8 = (f & 7) * 8;
            uint32_t so = (uint32_t)(row * FA_STR + c8) * 2;
            size_t go = gk + (size_t)row * D_MODEL + c8;
            CP16(base + so,           Kh_g + go);
            CP16(base + FT2 + so,     Kl_g + go);
            CP16(base + 2 * FT2 + so, Vh_g + go);
            CP16(base + 3 * FT2 + so, Vl_g + go);
        }
        CP_COMMIT();
    };

    float oacc[8][4];
#pragma unroll
    for (int nf = 0; nf < 8; nf++)
#pragma unroll
        for (int j = 0; j < 4; j++) oacc[nf][j] = 0.f;
    float m0 = -INFINITY, m1 = -INFINITY, l0 = 0.f, l1 = 0.f;

    load_kv(0, 0);

    for (int kt = 0; kt <= qt; kt++) {
        const int s = kt & 1;
        const uint32_t uKh = uKV0 + (uint32_t)s * 4 * FT2;
        const uint32_t uKl = uKh + FT2;
        const uint32_t uVh = uKh + 2 * FT2;
        const uint32_t uVl = uKh + 3 * FT2;

        CP_WAIT(0);        // current stage's copies arrived
        __syncthreads();   // all warps done with stage s^1 + copies visible
        if (kt < qt) load_kv(kt + 1, s ^ 1);   // prefetch overlaps compute below

        // ---- S = Qf K^T (fp16, 2-product) ----
        float sacc[8][4];
#pragma unroll
        for (int nf = 0; nf < 8; nf++)
#pragma unroll
            for (int j = 0; j < 4; j++) sacc[nf][j] = 0.f;

#pragma unroll
        for (int kc = 0; kc < 4; kc++) {
            const uint32_t aoff = (uint32_t)(((wr + (lane & 15)) * FA_STR
                                  + kc * 16 + (lane >> 4) * 8) * 2);
            uint32_t aqf[4];
            ldsm_x4(aqf, uQf + aoff);
            const uint32_t brow = (lane & 7);
            const uint32_t bk8  = ((lane >> 3) & 1) * 8;
#pragma unroll
            for (int nf = 0; nf < 8; nf++) {
                const uint32_t boff = (uint32_t)(((nf * 8 + brow) * FA_STR
                                      + kc * 16 + bk8) * 2);
                uint32_t bkh[2], bkl[2];
                ldsm_x2(bkh, uKh + boff);
                ldsm_x2(bkl, uKl + boff);
                mma16816h(sacc[nf], aqf, bkh);
                mma16816h(sacc[nf], aqf, bkl);
            }
        }

        // ---- causal mask (scale already folded into Q) ----
        if (kt == qt) {
#pragma unroll
            for (int nf = 0; nf < 8; nf++) {
                int col = nf * 8 + c0;
                int lrA = wr + r0, lrB = wr + r0 + 8;
                if (col     > lrA) sacc[nf][0] = -INFINITY;
                if (col + 1 > lrA) sacc[nf][1] = -INFINITY;
                if (col     > lrB) sacc[nf][2] = -INFINITY;
                if (col + 1 > lrB) sacc[nf][3] = -INFINITY;
            }
        }

        // ---- online softmax ----
        float mx0 = -INFINITY, mx1 = -INFINITY;
#pragma unroll
        for (int nf = 0; nf < 8; nf++) {
            mx0 = fmaxf(mx0, fmaxf(sacc[nf][0], sacc[nf][1]));
            mx1 = fmaxf(mx1, fmaxf(sacc[nf][2], sacc[nf][3]));
        }
        mx0 = fmaxf(mx0, __shfl_xor_sync(0xffffffffu, mx0, 1));
        mx0 = fmaxf(mx0, __shfl_xor_sync(0xffffffffu, mx0, 2));
        mx1 = fmaxf(mx1, __shfl_xor_sync(0xffffffffu, mx1, 1));
        mx1 = fmaxf(mx1, __shfl_xor_sync(0xffffffffu, mx1, 2));
        float mn0 = fmaxf(m0, mx0), mn1 = fmaxf(m1, mx1);
        float corr0 = __expf(m0 - mn0), corr1 = __expf(m1 - mn1);
        m0 = mn0; m1 = mn1;
        float rs0 = 0.f, rs1 = 0.f;
#pragma unroll
        for (int nf = 0; nf < 8; nf++) {
            sacc[nf][0] = __expf(sacc[nf][0] - m0);
            sacc[nf][1] = __expf(sacc[nf][1] - m0);
            sacc[nf][2] = __expf(sacc[nf][2] - m1);
            sacc[nf][3] = __expf(sacc[nf][3] - m1);
            rs0 += sacc[nf][0] + sacc[nf][1];
            rs1 += sacc[nf][2] + sacc[nf][3];
        }
        rs0 += __shfl_xor_sync(0xffffffffu, rs0, 1);
        rs0 += __shfl_xor_sync(0xffffffffu, rs0, 2);
        rs1 += __shfl_xor_sync(0xffffffffu, rs1, 1);
        rs1 += __shfl_xor_sync(0xffffffffu, rs1, 2);
        l0 = l0 * corr0 + rs0;
        l1 = l1 * corr1 + rs1;
#pragma unroll
        for (int nf = 0; nf < 8; nf++) {
            oacc[nf][0] *= corr0; oacc[nf][1] *= corr0;
            oacc[nf][2] *= corr1; oacc[nf][3] *= corr1;
        }

        // ---- O += P V : P single fp16, V fp16 hi/lo (2-product) ----
#pragma unroll
        for (int kc = 0; kc < 4; kc++) {
            uint32_t apf[4];
            apf[0] = pack2h(sacc[2 * kc][0],     sacc[2 * kc][1]);
            apf[1] = pack2h(sacc[2 * kc][2],     sacc[2 * kc][3]);
            apf[2] = pack2h(sacc[2 * kc + 1][0], sacc[2 * kc + 1][1]);
            apf[3] = pack2h(sacc[2 * kc + 1][2], sacc[2 * kc + 1][3]);
            const uint32_t vrow = (uint32_t)(kc * 16 + (lane & 15));
#pragma unroll
            for (int nf = 0; nf < 8; nf++) {
                const uint32_t voff = (uint32_t)((vrow * FA_STR + nf * 8) * 2);
                uint32_t bvh[2], bvl[2];
                ldsm_x2t(bvh, uVh + voff);
                ldsm_x2t(bvl, uVl + voff);
                mma16816h(oacc[nf], apf, bvh);
                mma16816h(oacc[nf], apf, bvl);
            }
        }
    }

    // ---- epilogue: normalize, store single fp16 ----
    float inv0 = 1.f / l0, inv1 = 1.f / l1;
    const size_t goA = (qrow0 + wr + r0) * D_MODEL + (size_t)h * HEAD_D;
    const size_t goB = goA + 8 * D_MODEL;
#pragma unroll
    for (int nf = 0; nf < 8; nf++) {
        int d = nf * 8 + c0;
        *(uint32_t*)(Of_g + goA + d) = pack2h(oacc[nf][0] * inv0, oacc[nf][1] * inv0);
        *(uint32_t*)(Of_g + goB + d) = pack2h(oacc[nf][2] * inv1, oacc[nf][3] * inv1);
    }
}

// ---------------------------------------------------------------------------
// kernel_launch: split(1) -> gemm_qkv(1) -> flash(1) -> gemm_o(1)
// ---------------------------------------------------------------------------
extern "C" void kernel_launch(void* const* d_in, const int* in_sizes, int n_in,
                              void* d_out, int out_size)
{
    const float* queries = (const float*)d_in[0];
    const float* keys    = (const float*)d_in[1];
    const float* values  = (const float*)d_in[2];
    const float* Wq = (const float*)d_in[3];
    const float* bq = (const float*)d_in[4];
    const float* Wk = (const float*)d_in[5];
    const float* bk = (const float*)d_in[6];
    const float* Wv = (const float*)d_in[7];
    const float* bv = (const float*)d_in[8];
    const float* Wo = (const float*)d_in[9];
    const float* bo = (const float*)d_in[10];
    float* out = (float*)d_out;

    __half *xf, *wf, *qf, *kh, *kl, *vh, *vl, *af;
    cudaGetSymbolAddress((void**)&xf, g_xf);
    cudaGetSymbolAddress((void**)&wf, g_wf);
    cudaGetSymbolAddress((void**)&qf, g_qf);
    cudaGetSymbolAddress((void**)&kh, g_kh);
    cudaGetSymbolAddress((void**)&kl, g_kl);
    cudaGetSymbolAddress((void**)&vh, g_vh);
    cudaGetSymbolAddress((void**)&vl, g_vl);
    cudaGetSymbolAddress((void**)&af, g_af);

    cudaFuncSetAttribute(flash_mma_kernel,
                         cudaFuncAttributeMaxDynamicSharedMemorySize, FA_SMEM);
    cudaFuncSetAttribute(gemm_qkv_kernel,
                         cudaFuncAttributeMaxDynamicSharedMemorySize, GSMEM);
    cudaFuncSetAttribute(gemm_o_kernel,
                         cudaFuncAttributeMaxDynamicSharedMemorySize, GSMEM);

    // 1) Fused split of all 7 tensors (single fp16)
    dim3 sGrd((unsigned)(XSZ / 4 / 1024), 7);
    split_all_kernel<<<sGrd, 256>>>(queries, keys, values, Wq, Wk, Wv, Wo, xf, wf);

    // 2) Batched Q/K/V projections (Q: fp16 pre-scaled; K/V: fp16 hi/lo)
    dim3 gGrd(D_MODEL / 128, MTOT / 128, 3);   // (8, 32, 3)
    gemm_qkv_kernel<<<gGrd, 256, GSMEM>>>(xf, wf, bq, bk, bv,
                                          qf, kh, kl, vh, vl);

    // 3) Attention (64-row Q tiles, heaviest CTAs first)
    dim3 aGrd(LSEQ / 64, N_HEADS, NB);         // (32, 16, 2)
    flash_mma_kernel<<<aGrd, 128, FA_SMEM>>>(qf, kh, kl, vh, vl, af);

    // 4) Output projection: fp32 out
    dim3 oGrd(D_MODEL / 128, MTOT / 128);      // (8, 32)
    gemm_o_kernel<<<oGrd, 256, GSMEM>>>(af, wf + 3 * WSZ, bo, out);
}